// round 15
// baseline (speedup 1.0000x reference)
#include <cuda_runtime.h>
#include <cuda_fp16.h>
#include <math.h>
#include <stdint.h>

// ---------------- problem constants ----------------
#define DIMN 2048
#define HEADS 16
#define HD 128
#define RANKN 64
#define IMG_SEQ 2048
#define TXT_SEQ 128
#define SEQN 2176          // IMG_SEQ + TXT_SEQ
#define CONDN 1024
#define BLOCKN 1024        // IMG_SEQ - COND
#define SBSN 1152          // SEQ - COND
#define EPSV 1e-5f

// ---------------- device scratch (no allocation allowed) ----------------
__device__ float g_Q[SEQN * DIMN];
__device__ float g_K[SEQN * DIMN];
__device__ float g_part[8 * CONDN * 192];
__device__ __half g_Ah[SEQN * DIMN];    // fp16 [img; txt] activations
__device__ __half g_Oh[SEQN * DIMN];    // fp16 attention output
__device__ __half g_Qh[SEQN * DIMN];
__device__ __half g_Kh[SEQN * DIMN];
__device__ __half g_Vth[DIMN * SEQN];   // per head: [d=128][seq] fp16

// ---------------- helpers ----------------
__device__ __forceinline__ uint32_t pack_h2(float x, float y) {
    __half2 h = __floats2half2_rn(x, y);
    return *(uint32_t*)&h;
}

__device__ __forceinline__ void mma_f16(float c[4], const uint32_t a[4],
                                        uint32_t b0, uint32_t b1) {
    asm volatile(
        "mma.sync.aligned.m16n8k16.row.col.f32.f16.f16.f32 "
        "{%0,%1,%2,%3}, {%4,%5,%6,%7}, {%8,%9}, {%0,%1,%2,%3};"
        : "+f"(c[0]), "+f"(c[1]), "+f"(c[2]), "+f"(c[3])
        : "r"(a[0]), "r"(a[1]), "r"(a[2]), "r"(a[3]),
          "r"(b0), "r"(b1));
}

__device__ __forceinline__ void ldsm4(uint32_t& r0, uint32_t& r1,
                                      uint32_t& r2, uint32_t& r3, uint32_t addr) {
    asm volatile("ldmatrix.sync.aligned.m8n8.x4.shared.b16 {%0,%1,%2,%3}, [%4];"
                 : "=r"(r0), "=r"(r1), "=r"(r2), "=r"(r3) : "r"(addr));
}

__device__ __forceinline__ void cp_async16(uint32_t dst_smem, const void* src) {
    asm volatile("cp.async.cg.shared.global [%0], [%1], 16;"
                 :: "r"(dst_smem), "l"(src));
}
__device__ __forceinline__ void cp_commit() {
    asm volatile("cp.async.commit_group;" ::: "memory");
}
template <int N>
__device__ __forceinline__ void cp_wait() {
    asm volatile("cp.async.wait_group %0;" :: "n"(N) : "memory");
}

#define HLD 40   // halves per smem row (20 words -> conflict-free ldmatrix)

// ---------------- fp32 -> fp16 streaming convert (img ++ txt) ---------------
__global__ __launch_bounds__(256) void tofp16_kernel(const float* __restrict__ a,
                                                     const float* __restrict__ b,
                                                     int na4, int tot4,
                                                     __half* __restrict__ dst) {
    int i = blockIdx.x * blockDim.x + threadIdx.x;
    if (i >= tot4) return;
    const float* src = (i < na4) ? &a[(size_t)i * 4] : &b[(size_t)(i - na4) * 4];
    float4 v = *(const float4*)src;
    *(uint2*)&dst[(size_t)i * 4] = make_uint2(pack_h2(v.x, v.y), pack_h2(v.z, v.w));
}

// ===== async fp16 projection GEMM + fused LoRA-up + optional V-transpose ====
#define PJ_AS0 0
#define PJ_AS1 10240
#define PJ_BS  20480
#define PJ_BST0 30720
#define PJ_BST1 47104
#define PJ_BYTES 63488

__global__ __launch_bounds__(256, 2) void proj_gemm3h(
    const __half* __restrict__ Ain,
    const float* __restrict__ Wa0, const float* __restrict__ Wb0, float* __restrict__ C0,
    const float* __restrict__ Wa1, const float* __restrict__ Wb1, float* __restrict__ C1,
    const float* __restrict__ Wa2, const float* __restrict__ Wb2,
    __half* __restrict__ Vth,          // z==2 output when vth!=0
    const float* __restrict__ part,
    const float* __restrict__ up0, const float* __restrict__ up1,
    const float* __restrict__ up2,
    int Msplit, int N, int K, int lora, int remap, int vth) {
    extern __shared__ char smc[];
    const uint32_t sbase = (uint32_t)__cvta_generic_to_shared(smc);
    __half* Bs = (__half*)(smc + PJ_BS);
    const uint32_t bs_base = sbase + PJ_BS;

    const int tid = threadIdx.x;
    const int lane = tid & 31;
    const int warp = tid >> 5;
    const int wm = warp & 3;
    const int wn = warp >> 2;
    const int lrow = lane >> 2;
    const int lcol = lane & 3;
    const int row0 = blockIdx.y * 128;
    const int col0 = blockIdx.x * 128;
    const int z = blockIdx.z;

    const float* W;
    float* C;
    const float* up;
    if (z == 0)      { W = (row0 < Msplit) ? Wa0 : Wb0; C = C0; up = up0; }
    else if (z == 1) { W = (row0 < Msplit) ? Wa1 : Wb1; C = C1; up = up1; }
    else             { W = (row0 < Msplit) ? Wa2 : Wb2; C = C0; up = up2; }

    int row_out0 = row0;
    if (remap) {
        if (row0 >= IMG_SEQ)      row_out0 = row0 - CONDN;
        else if (row0 >= BLOCKN)  row_out0 = row0 + TXT_SEQ;
    }

    float c[2][8][4];
#pragma unroll
    for (int i = 0; i < 2; i++)
#pragma unroll
        for (int j = 0; j < 8; j++)
#pragma unroll
            for (int r = 0; r < 4; r++) c[i][j][r] = 0.f;

    const int al_row = wm * 32 + (lane & 15);
    const int al_k   = 8 * (lane >> 4);
    const int bl_tile = lane >> 4;
    const int bl_row  = lane & 7;
    const int bl_k    = 8 * ((lane >> 3) & 1);

    auto compute_block = [&](uint32_t a_base) {
#pragma unroll
        for (int ks = 0; ks < 2; ks++) {
            const int kb = ks * 16;
            uint32_t a[2][4];
#pragma unroll
            for (int mi = 0; mi < 2; mi++) {
                uint32_t addr = a_base +
                    (uint32_t)(((al_row + mi * 16) * HLD) + kb + al_k) * 2;
                ldsm4(a[mi][0], a[mi][1], a[mi][2], a[mi][3], addr);
            }
            uint32_t b[8][2];
#pragma unroll
            for (int j = 0; j < 4; j++) {
                int brow = wn * 64 + (2 * j + bl_tile) * 8 + bl_row;
                uint32_t addr = bs_base + (uint32_t)(brow * HLD + kb + bl_k) * 2;
                ldsm4(b[2 * j][0], b[2 * j][1], b[2 * j + 1][0], b[2 * j + 1][1], addr);
            }
#pragma unroll
            for (int mi = 0; mi < 2; mi++)
#pragma unroll
                for (int ni = 0; ni < 8; ni++)
                    mma_f16(c[mi][ni], a[mi], b[ni][0], b[ni][1]);
        }
    };

    auto issue_tile = [&](int kt, int stg) {
        const int k0 = kt * 32;
        const __half* asrc = Ain + (size_t)row0 * K + k0;
        const uint32_t adst = sbase + (stg ? PJ_AS1 : PJ_AS0);
#pragma unroll
        for (int f = 0; f < 2; f++) {
            int id = tid + f * 256;
            int r = id >> 2;
            int cc = id & 3;
            cp_async16(adst + (uint32_t)(r * 80 + cc * 16),
                       asrc + (size_t)r * K + cc * 8);
        }
        const float* wsrc = W + (size_t)col0 * K + k0;
        const uint32_t bdst = sbase + (stg ? PJ_BST1 : PJ_BST0);
#pragma unroll
        for (int f = 0; f < 4; f++) {
            int id = tid + f * 256;
            int r = id >> 3;
            int cc = id & 7;
            cp_async16(bdst + (uint32_t)(r * 128 + cc * 16),
                       wsrc + (size_t)r * K + cc * 4);
        }
        cp_commit();
    };

    auto convert_B = [&](int stg) {
        const float* bst = (const float*)(smc + (stg ? PJ_BST1 : PJ_BST0));
#pragma unroll
        for (int f = 0; f < 4; f++) {
            int id = tid + f * 256;
            int r = id >> 3;
            int kq = (id & 7) << 2;
            float4 v = *(const float4*)&bst[r * 32 + kq];
            *(uint2*)&Bs[r * HLD + kq] =
                make_uint2(pack_h2(v.x, v.y), pack_h2(v.z, v.w));
        }
    };

    const int iters = K / 32;
    issue_tile(0, 0);

    for (int it = 0; it < iters; it++) {
        const int stg = it & 1;
        if (it + 1 < iters) {
            issue_tile(it + 1, stg ^ 1);
            cp_wait<1>();
        } else {
            cp_wait<0>();
        }
        convert_B(stg);
        __syncthreads();
        compute_block(sbase + (stg ? PJ_AS1 : PJ_AS0));
        __syncthreads();
    }

    if (lora && row0 >= BLOCKN && row0 < IMG_SEQ) {
        __half* As0 = (__half*)(smc + PJ_AS0);
        const int arow0 = row0 - BLOCKN;
#pragma unroll
        for (int e = 0; e < 2; e++) {
            const int k0 = e * 32;
#pragma unroll
            for (int f = 0; f < 4; f++) {
                int id = tid + f * 256;
                int r = id >> 3;
                int kq = (id & 7) << 2;
                const float* pa = part + (size_t)(arow0 + r) * 192 + z * 64 + k0 + kq;
                float4 va = *(const float4*)pa;
#pragma unroll
                for (int s = 1; s < 8; s++) {
                    float4 t = *(const float4*)(pa + (size_t)s * CONDN * 192);
                    va.x += t.x; va.y += t.y; va.z += t.z; va.w += t.w;
                }
                *(uint2*)&As0[r * HLD + kq] =
                    make_uint2(pack_h2(va.x, va.y), pack_h2(va.z, va.w));
                float4 vb = *(const float4*)&up[(size_t)(col0 + r) * 64 + k0 + kq];
                *(uint2*)&Bs[r * HLD + kq] =
                    make_uint2(pack_h2(vb.x, vb.y), pack_h2(vb.z, vb.w));
            }
            __syncthreads();
            compute_block(sbase + PJ_AS0);
            __syncthreads();
        }
    }

    if (vth && z == 2) {
        // V output: write transposed fp16 into Vth[head][d][seq]
        const int head = col0 >> 7;
        __half* vbase = Vth + (size_t)head * 128 * SEQN;
#pragma unroll
        for (int mi = 0; mi < 2; mi++)
#pragma unroll
            for (int ni = 0; ni < 8; ni++) {
                int gr = row0 + wm * 32 + mi * 16 + lrow;
                int d0 = (wn * 64 + ni * 8 + lcol * 2) & 127;
                vbase[(size_t)d0 * SEQN + gr]       = __float2half_rn(c[mi][ni][0]);
                vbase[(size_t)(d0 + 1) * SEQN + gr] = __float2half_rn(c[mi][ni][1]);
                vbase[(size_t)d0 * SEQN + gr + 8]       = __float2half_rn(c[mi][ni][2]);
                vbase[(size_t)(d0 + 1) * SEQN + gr + 8] = __float2half_rn(c[mi][ni][3]);
            }
    } else {
#pragma unroll
        for (int mi = 0; mi < 2; mi++)
#pragma unroll
            for (int ni = 0; ni < 8; ni++) {
                int gr = row_out0 + wm * 32 + mi * 16 + lrow;
                int gc = col0 + wn * 64 + ni * 8 + lcol * 2;
                *(float2*)&C[(size_t)gr * N + gc] =
                    make_float2(c[mi][ni][0], c[mi][ni][1]);
                *(float2*)&C[(size_t)(gr + 8) * N + gc] =
                    make_float2(c[mi][ni][2], c[mi][ni][3]);
            }
    }
}

// ===== fp16 LoRA up-projection with inline 8-way partial sum ================
__global__ __launch_bounds__(256) void up_sum_gemm_acc_h(
    const float* __restrict__ part,
    const float* __restrict__ W,
    float* __restrict__ C, int N) {
    __shared__ __half As[128 * HLD];
    __shared__ __half Bs[128 * HLD];

    const int tid = threadIdx.x;
    const int lane = tid & 31;
    const int warp = tid >> 5;
    const int wm = warp & 3;
    const int wn = warp >> 2;
    const int lrow = lane >> 2;
    const int lcol = lane & 3;
    const int row0 = blockIdx.y * 128;
    const int col0 = blockIdx.x * 128;

    float c[2][8][4];
#pragma unroll
    for (int i = 0; i < 2; i++)
#pragma unroll
        for (int j = 0; j < 8; j++)
#pragma unroll
            for (int r = 0; r < 4; r++) c[i][j][r] = 0.f;

    for (int k0 = 0; k0 < 64; k0 += 32) {
#pragma unroll
        for (int f = 0; f < 4; f++) {
            int id = tid + f * 256;
            int r = id >> 3;
            int kq = (id & 7) << 2;
            const float* pa = part + (size_t)(row0 + r) * 64 + k0 + kq;
            float4 va = *(const float4*)pa;
#pragma unroll
            for (int s = 1; s < 8; s++) {
                float4 t = *(const float4*)(pa + (size_t)s * CONDN * 64);
                va.x += t.x; va.y += t.y; va.z += t.z; va.w += t.w;
            }
            *(uint2*)&As[r * HLD + kq] =
                make_uint2(pack_h2(va.x, va.y), pack_h2(va.z, va.w));
            float4 vb = *(const float4*)&W[(size_t)(col0 + r) * 64 + k0 + kq];
            *(uint2*)&Bs[r * HLD + kq] =
                make_uint2(pack_h2(vb.x, vb.y), pack_h2(vb.z, vb.w));
        }
        __syncthreads();

#pragma unroll
        for (int ks = 0; ks < 2; ks++) {
            const int kb = ks * 16 + 2 * lcol;
            uint32_t a[2][4];
#pragma unroll
            for (int mi = 0; mi < 2; mi++) {
                int ar = wm * 32 + mi * 16 + lrow;
                a[mi][0] = *(const uint32_t*)&As[ar * HLD + kb];
                a[mi][1] = *(const uint32_t*)&As[(ar + 8) * HLD + kb];
                a[mi][2] = *(const uint32_t*)&As[ar * HLD + kb + 8];
                a[mi][3] = *(const uint32_t*)&As[(ar + 8) * HLD + kb + 8];
            }
            uint32_t b[8][2];
#pragma unroll
            for (int ni = 0; ni < 8; ni++) {
                int br = wn * 64 + ni * 8 + lrow;
                b[ni][0] = *(const uint32_t*)&Bs[br * HLD + kb];
                b[ni][1] = *(const uint32_t*)&Bs[br * HLD + kb + 8];
            }
#pragma unroll
            for (int mi = 0; mi < 2; mi++)
#pragma unroll
                for (int ni = 0; ni < 8; ni++)
                    mma_f16(c[mi][ni], a[mi], b[ni][0], b[ni][1]);
        }
        __syncthreads();
    }

#pragma unroll
    for (int mi = 0; mi < 2; mi++)
#pragma unroll
        for (int ni = 0; ni < 8; ni++) {
            int gr = row0 + wm * 32 + mi * 16 + lrow;
            int gc = col0 + wn * 64 + ni * 8 + lcol * 2;
            float2* p0 = (float2*)&C[(size_t)gr * N + gc];
            float2* p1 = (float2*)&C[(size_t)(gr + 8) * N + gc];
            float2 o0 = *p0, o1 = *p1;
            o0.x += c[mi][ni][0]; o0.y += c[mi][ni][1];
            o1.x += c[mi][ni][2]; o1.y += c[mi][ni][3];
            *p0 = o0; *p1 = o1;
        }
}

// ===== split-K LoRA down-projection, templated A type ========================
template <typename TA>
__global__ __launch_bounds__(256) void down_gemm_t(const TA* __restrict__ A,
                                                   const float* __restrict__ w0,
                                                   const float* __restrict__ w1,
                                                   const float* __restrict__ w2,
                                                   float* __restrict__ part,
                                                   int M, int Ntot, int Kfull) {
    __shared__ __half As[128 * HLD];
    __shared__ __half Ws[64 * HLD];

    const int cb = blockIdx.x, mb = blockIdx.y, sp = blockIdx.z;
    const int Kc = Kfull >> 3;
    const int kbase = sp * Kc;
    const float* W = (cb == 0) ? w0 : (cb == 1 ? w1 : w2);

    const int tid = threadIdx.x;
    const int lane = tid & 31;
    const int warp = tid >> 5;
    const int wm = warp & 3;
    const int wn = warp >> 2;
    const int lrow = lane >> 2;
    const int lcol = lane & 3;

    float c[2][4][4];
#pragma unroll
    for (int i = 0; i < 2; i++)
#pragma unroll
        for (int j = 0; j < 4; j++)
#pragma unroll
            for (int r = 0; r < 4; r++) c[i][j][r] = 0.f;

    for (int k0 = 0; k0 < Kc; k0 += 32) {
#pragma unroll
        for (int f = 0; f < 4; f++) {
            int id = tid + f * 256;
            int r = id >> 3;
            int kq = (id & 7) << 2;
            const TA* pa = &A[(size_t)(mb * 128 + r) * Kfull + kbase + k0 + kq];
            if (sizeof(TA) == 2) {
                *(uint2*)&As[r * HLD + kq] = *(const uint2*)pa;
            } else {
                float4 va = *(const float4*)pa;
                *(uint2*)&As[r * HLD + kq] =
                    make_uint2(pack_h2(va.x, va.y), pack_h2(va.z, va.w));
            }
        }
#pragma unroll
        for (int f = 0; f < 2; f++) {
            int id = tid + f * 256;
            int r = id >> 3;
            int kq = (id & 7) << 2;
            float4 vb = *(const float4*)&W[(size_t)r * Kfull + kbase + k0 + kq];
            *(uint2*)&Ws[r * HLD + kq] =
                make_uint2(pack_h2(vb.x, vb.y), pack_h2(vb.z, vb.w));
        }
        __syncthreads();

#pragma unroll
        for (int ks = 0; ks < 2; ks++) {
            const int kb = ks * 16 + 2 * lcol;
            uint32_t a[2][4];
#pragma unroll
            for (int mi = 0; mi < 2; mi++) {
                int ar = wm * 32 + mi * 16 + lrow;
                a[mi][0] = *(const uint32_t*)&As[ar * HLD + kb];
                a[mi][1] = *(const uint32_t*)&As[(ar + 8) * HLD + kb];
                a[mi][2] = *(const uint32_t*)&As[ar * HLD + kb + 8];
                a[mi][3] = *(const uint32_t*)&As[(ar + 8) * HLD + kb + 8];
            }
            uint32_t b[4][2];
#pragma unroll
            for (int ni = 0; ni < 4; ni++) {
                int br = wn * 32 + ni * 8 + lrow;
                b[ni][0] = *(const uint32_t*)&Ws[br * HLD + kb];
                b[ni][1] = *(const uint32_t*)&Ws[br * HLD + kb + 8];
            }
#pragma unroll
            for (int mi = 0; mi < 2; mi++)
#pragma unroll
                for (int ni = 0; ni < 4; ni++)
                    mma_f16(c[mi][ni], a[mi], b[ni][0], b[ni][1]);
        }
        __syncthreads();
    }

    float* basep = part + (size_t)sp * M * Ntot;
#pragma unroll
    for (int mi = 0; mi < 2; mi++)
#pragma unroll
        for (int ni = 0; ni < 4; ni++) {
            int gr = mb * 128 + wm * 32 + mi * 16 + lrow;
            int gc = cb * 64 + wn * 32 + ni * 8 + lcol * 2;
            *(float2*)&basep[(size_t)gr * Ntot + gc] =
                make_float2(c[mi][ni][0], c[mi][ni][1]);
            *(float2*)&basep[(size_t)(gr + 8) * Ntot + gc] =
                make_float2(c[mi][ni][2], c[mi][ni][3]);
        }
}

// ---------------- fused RMS + rope -> fp16 Qh (pre-scaled), Kh --------------
__global__ __launch_bounds__(256) void rmsrope_kernel(
    const float* __restrict__ Q, const float* __restrict__ K,
    __half* __restrict__ Qh, __half* __restrict__ Kh,
    const float* __restrict__ rope,
    const float* __restrict__ gq, const float* __restrict__ gk,
    const float* __restrict__ gqt, const float* __restrict__ gkt) {
    const int row = blockIdx.x;
    const int tid = threadIdx.x;
    __shared__ float sbuf[18];

    const float* qrow = Q + (size_t)row * DIMN;
    const float* krow = K + (size_t)row * DIMN;
    __half* qh = Qh + (size_t)row * DIMN;
    __half* kh = Kh + (size_t)row * DIMN;

    float sq = 0.f, sk = 0.f;
    for (int c4 = tid; c4 < DIMN / 4; c4 += 256) {
        float4 q = *(const float4*)&qrow[c4 * 4];
        sq += q.x * q.x + q.y * q.y + q.z * q.z + q.w * q.w;
        float4 kk = *(const float4*)&krow[c4 * 4];
        sk += kk.x * kk.x + kk.y * kk.y + kk.z * kk.z + kk.w * kk.w;
    }
#pragma unroll
    for (int o = 16; o > 0; o >>= 1) {
        sq += __shfl_xor_sync(0xffffffffu, sq, o);
        sk += __shfl_xor_sync(0xffffffffu, sk, o);
    }
    int w = tid >> 5;
    if ((tid & 31) == 0) { sbuf[w] = sq; sbuf[8 + w] = sk; }
    __syncthreads();
    if (tid == 0) {
        float a = 0.f, b = 0.f;
        for (int i = 0; i < 8; i++) { a += sbuf[i]; b += sbuf[8 + i]; }
        sbuf[16] = a; sbuf[17] = b;
    }
    __syncthreads();
    const float scale = 0.08838834764831844f;
    const float invq = rsqrtf(sbuf[16] / (float)DIMN + EPSV);
    const float invk = rsqrtf(sbuf[17] / (float)DIMN + EPSV);
    const float* gQ = (row < IMG_SEQ) ? gq : gqt;
    const float* gK = (row < IMG_SEQ) ? gk : gkt;
    const float* rp = rope + (size_t)row * 256;

    for (int pi = tid; pi < DIMN / 2; pi += 256) {
        int c0 = pi * 2;
        int j = pi & 63;
        float4 r = *(const float4*)&rp[j * 4];
        float x0 = qrow[c0] * invq * gQ[c0];
        float x1 = qrow[c0 + 1] * invq * gQ[c0 + 1];
        *(uint32_t*)&qh[c0] = pack_h2(scale * (r.x * x0 + r.y * x1),
                                      scale * (r.z * x0 + r.w * x1));
        float y0 = krow[c0] * invk * gK[c0];
        float y1 = krow[c0 + 1] * invk * gK[c0 + 1];
        *(uint32_t*)&kh[c0] = pack_h2(r.x * y0 + r.y * y1,
                                      r.z * y0 + r.w * y1);
    }
}

// ------- flash attention: register-resident P (no Ps smem round-trip) -------
#define KLD 136
#define VLD 72
#define FB_KS0 0
#define FB_KS1 17408
#define FB_VT0 34816
#define FB_VT1 53248
#define FB_BYTES 71680

__global__ __launch_bounds__(256) void flash_mma(const __half* __restrict__ Qh,
                                                 const __half* __restrict__ Kh,
                                                 const __half* __restrict__ Vth,
                                                 __half* __restrict__ Oh) {
    extern __shared__ char smc[];
    const uint32_t sbase = (uint32_t)__cvta_generic_to_shared(smc);

    const int tid = threadIdx.x;
    const int lane = tid & 31;
    const int warp = tid >> 5;
    const int lrow = lane >> 2;
    const int lcol = lane & 3;
    const int qrow0 = blockIdx.x * 128;
    const int head = blockIdx.y;
    const size_t hoff = (size_t)head * HD;
    const __half* Vh = Vth + (size_t)head * 128 * SEQN;

    const int bl_tile = lane >> 4;
    const int bl_row  = lane & 7;
    const int bl_k    = 8 * ((lane >> 3) & 1);

    uint32_t qa[8][4];
    {
        const __half* qb = Qh + (size_t)(qrow0 + warp * 16) * DIMN + hoff;
#pragma unroll
        for (int ks = 0; ks < 8; ks++) {
            int kb = ks * 16 + 2 * lcol;
            qa[ks][0] = *(const uint32_t*)&qb[(size_t)lrow * DIMN + kb];
            qa[ks][1] = *(const uint32_t*)&qb[(size_t)(lrow + 8) * DIMN + kb];
            qa[ks][2] = *(const uint32_t*)&qb[(size_t)lrow * DIMN + kb + 8];
            qa[ks][3] = *(const uint32_t*)&qb[(size_t)(lrow + 8) * DIMN + kb + 8];
        }
    }

    float o[16][4];
#pragma unroll
    for (int ni = 0; ni < 16; ni++)
#pragma unroll
        for (int r = 0; r < 4; r++) o[ni][r] = 0.f;
    float m0 = -INFINITY, m1 = -INFINITY, l0 = 0.f, l1 = 0.f;

    const int kt0 = (qrow0 >= SBSN) ? (SBSN / 64) : 0;
    const int ktN = SEQN / 64;

    auto issue_tile = [&](int kt, int stg) {
        const int kr0 = kt * 64;
        const __half* ksrc = Kh + (size_t)kr0 * DIMN + hoff;
        const uint32_t kdst = sbase + (stg ? FB_KS1 : FB_KS0);
#pragma unroll
        for (int f = 0; f < 4; f++) {
            int id = tid + f * 256;
            int r = id >> 4;
            int cc = id & 15;
            cp_async16(kdst + (uint32_t)(r * KLD + cc * 8) * 2,
                       ksrc + (size_t)r * DIMN + cc * 8);
        }
        const __half* vsrc = Vh + kr0;
        const uint32_t vdst = sbase + (stg ? FB_VT1 : FB_VT0);
#pragma unroll
        for (int f = 0; f < 4; f++) {
            int id = tid + f * 256;
            int d = id >> 3;
            int cc = id & 7;
            cp_async16(vdst + (uint32_t)(d * VLD + cc * 8) * 2,
                       vsrc + (size_t)d * SEQN + cc * 8);
        }
        cp_commit();
    };

    issue_tile(kt0, kt0 & 1);

    for (int kt = kt0; kt < ktN; kt++) {
        const int stg = kt & 1;
        if (kt + 1 < ktN) {
            issue_tile(kt + 1, stg ^ 1);
            cp_wait<1>();
        } else {
            cp_wait<0>();
        }
        __syncthreads();
        const uint32_t ks_base = sbase + (stg ? FB_KS1 : FB_KS0);
        const uint32_t vt_base = sbase + (stg ? FB_VT1 : FB_VT0);

        float s[8][4];
#pragma unroll
        for (int ni = 0; ni < 8; ni++)
#pragma unroll
            for (int r = 0; r < 4; r++) s[ni][r] = 0.f;
#pragma unroll
        for (int ks = 0; ks < 8; ks++) {
            const int kb = ks * 16;
            uint32_t b[8][2];
#pragma unroll
            for (int j = 0; j < 4; j++) {
                int brow = (2 * j + bl_tile) * 8 + bl_row;
                uint32_t addr = ks_base + (uint32_t)(brow * KLD + kb + bl_k) * 2;
                ldsm4(b[2 * j][0], b[2 * j][1], b[2 * j + 1][0], b[2 * j + 1][1], addr);
            }
#pragma unroll
            for (int ni = 0; ni < 8; ni++)
                mma_f16(s[ni], qa[ks], b[ni][0], b[ni][1]);
        }

        float mt0 = -INFINITY, mt1 = -INFINITY;
#pragma unroll
        for (int ni = 0; ni < 8; ni++) {
            mt0 = fmaxf(mt0, fmaxf(s[ni][0], s[ni][1]));
            mt1 = fmaxf(mt1, fmaxf(s[ni][2], s[ni][3]));
        }
#pragma unroll
        for (int off = 1; off <= 2; off <<= 1) {
            mt0 = fmaxf(mt0, __shfl_xor_sync(0xffffffffu, mt0, off));
            mt1 = fmaxf(mt1, __shfl_xor_sync(0xffffffffu, mt1, off));
        }
        float mn0 = fmaxf(m0, mt0), mn1 = fmaxf(m1, mt1);
        float corr0 = __expf(m0 - mn0), corr1 = __expf(m1 - mn1);
        m0 = mn0; m1 = mn1;

        uint32_t ph[8][2];
        float ps0 = 0.f, ps1 = 0.f;
#pragma unroll
        for (int ni = 0; ni < 8; ni++) {
            __half2 h01 = __floats2half2_rn(__expf(s[ni][0] - mn0),
                                            __expf(s[ni][1] - mn0));
            __half2 h23 = __floats2half2_rn(__expf(s[ni][2] - mn1),
                                            __expf(s[ni][3] - mn1));
            ps0 += __low2float(h01) + __high2float(h01);
            ps1 += __low2float(h23) + __high2float(h23);
            ph[ni][0] = *(uint32_t*)&h01;
            ph[ni][1] = *(uint32_t*)&h23;
        }
#pragma unroll
        for (int off = 1; off <= 2; off <<= 1) {
            ps0 += __shfl_xor_sync(0xffffffffu, ps0, off);
            ps1 += __shfl_xor_sync(0xffffffffu, ps1, off);
        }
        l0 = l0 * corr0 + ps0;
        l1 = l1 * corr1 + ps1;
#pragma unroll
        for (int ni = 0; ni < 16; ni++) {
            o[ni][0] *= corr0; o[ni][1] *= corr0;
            o[ni][2] *= corr1; o[ni][3] *= corr1;
        }

#pragma unroll
        for (int ks = 0; ks < 4; ks++) {
            const int kb = ks * 16;
            uint32_t a[4];
            a[0] = ph[2 * ks][0];
            a[1] = ph[2 * ks][1];
            a[2] = ph[2 * ks + 1][0];
            a[3] = ph[2 * ks + 1][1];
#pragma unroll
            for (int j = 0; j < 8; j++) {
                int brow = (2 * j + bl_tile) * 8 + bl_row;
                uint32_t addr = vt_base + (uint32_t)(brow * VLD + kb + bl_k) * 2;
                uint32_t b0, b1, b2, b3;
                ldsm4(b0, b1, b2, b3, addr);
                mma_f16(o[2 * j], a, b0, b1);
                mma_f16(o[2 * j + 1], a, b2, b3);
            }
        }
        __syncthreads();
    }

    const float inv0 = 1.f / l0, inv1 = 1.f / l1;
    const int gr0 = qrow0 + warp * 16 + lrow;
#pragma unroll
    for (int ni = 0; ni < 16; ni++) {
        int gc = ni * 8 + lcol * 2;
        *(uint32_t*)&Oh[(size_t)gr0 * DIMN + hoff + gc] =
            pack_h2(o[ni][0] * inv0, o[ni][1] * inv0);
        *(uint32_t*)&Oh[(size_t)(gr0 + 8) * DIMN + hoff + gc] =
            pack_h2(o[ni][2] * inv1, o[ni][3] * inv1);
    }
}

// ---------------- launch ----------------
extern "C" void kernel_launch(void* const* d_in, const int* in_sizes, int n_in,
                              void* d_out, int out_size) {
    const float* img  = (const float*)d_in[0];
    const float* txt  = (const float*)d_in[1];
    const float* rope = (const float*)d_in[2];
    const float* wq   = (const float*)d_in[3];
    const float* wk   = (const float*)d_in[4];
    const float* wv   = (const float*)d_in[5];
    const float* wo   = (const float*)d_in[6];
    const float* wq_t = (const float*)d_in[7];
    const float* wk_t = (const float*)d_in[8];
    const float* wv_t = (const float*)d_in[9];
    const float* wo_t = (const float*)d_in[10];
    const float* gq   = (const float*)d_in[11];
    const float* gk   = (const float*)d_in[12];
    const float* gqt  = (const float*)d_in[13];
    const float* gkt  = (const float*)d_in[14];
    const float* q_down = (const float*)d_in[15];
    const float* q_up   = (const float*)d_in[16];
    const float* k_down = (const float*)d_in[17];
    const float* k_up   = (const float*)d_in[18];
    const float* v_down = (const float*)d_in[19];
    const float* v_up   = (const float*)d_in[20];
    const float* p_down = (const float*)d_in[21];
    const float* p_up   = (const float*)d_in[22];
    float* out = (float*)d_out;

    float *Q, *K, *part;
    __half *Ah, *Oh, *Qh, *Kh, *Vth;
    cudaGetSymbolAddress((void**)&Q,    g_Q);
    cudaGetSymbolAddress((void**)&K,    g_K);
    cudaGetSymbolAddress((void**)&part, g_part);
    cudaGetSymbolAddress((void**)&Ah,   g_Ah);
    cudaGetSymbolAddress((void**)&Oh,   g_Oh);
    cudaGetSymbolAddress((void**)&Qh,   g_Qh);
    cudaGetSymbolAddress((void**)&Kh,   g_Kh);
    cudaGetSymbolAddress((void**)&Vth,  g_Vth);

    float* out_cond = out + (size_t)SBSN * DIMN;

    cudaFuncSetAttribute(proj_gemm3h, cudaFuncAttributeMaxDynamicSharedMemorySize,
                         PJ_BYTES);
    cudaFuncSetAttribute(flash_mma, cudaFuncAttributeMaxDynamicSharedMemorySize,
                         FB_BYTES);

    // 0) activations -> fp16 [img; txt]
    {
        int na4 = IMG_SEQ * DIMN / 4;
        int tot4 = SEQN * DIMN / 4;
        tofp16_kernel<<<(tot4 + 255) / 256, 256>>>(img, txt, na4, tot4, Ah);
    }

    // 1) fused LoRA down-projections (q/k/v), split-K 8-way -> partials
    down_gemm_t<__half><<<dim3(3, CONDN / 128, 8), 256>>>(
        Ah + (size_t)BLOCKN * DIMN, q_down, k_down, v_down,
        part, CONDN, 192, DIMN);

    // 2) QKV projections in ONE launch; V written transposed fp16 into Vth
    proj_gemm3h<<<dim3(DIMN / 128, SEQN / 128, 3), 256, PJ_BYTES>>>(
        Ah,
        wq, wq_t, Q,
        wk, wk_t, K,
        wv, wv_t, Vth,
        part, q_up, k_up, v_up,
        IMG_SEQ, DIMN, DIMN, 1, 0, 1);

    // 3) RMS + rope -> fp16 Qh (pre-scaled), Kh
    rmsrope_kernel<<<SEQN, 256>>>(Q, K, Qh, Kh, rope, gq, gk, gqt, gkt);

    // 4) flash attention (register-resident P) -> fp16 Oh
    flash_mma<<<dim3(SEQN / 128, HEADS), 256, FB_BYTES>>>(Qh, Kh, Vth, Oh);

    // 5) output projection, written DIRECTLY in output layout [img|text|cond]
    proj_gemm3h<<<dim3(DIMN / 128, SEQN / 128, 1), 256, PJ_BYTES>>>(
        Oh,
        wo, wo_t, out,
        wo, wo_t, out,
        wo, wo_t, (__half*)Vth,
        part, q_up, k_up, v_up,
        IMG_SEQ, DIMN, DIMN, 0, 1, 0);

    // 6) post-projection LoRA on cond region of out (down -> fused-sum up)
    down_gemm_t<float><<<dim3(1, CONDN / 128, 8), 256>>>(
        out_cond, p_down, p_down, p_down, part, CONDN, 64, DIMN);
    up_sum_gemm_acc_h<<<dim3(DIMN / 128, CONDN / 128), 256>>>(part, p_up,
                                                              out_cond, DIMN);
}

// round 16
// speedup vs baseline: 1.0913x; 1.0913x over previous
#include <cuda_runtime.h>
#include <cuda_fp16.h>
#include <math.h>
#include <stdint.h>

// ---------------- problem constants ----------------
#define DIMN 2048
#define HEADS 16
#define HD 128
#define RANKN 64
#define IMG_SEQ 2048
#define TXT_SEQ 128
#define SEQN 2176          // IMG_SEQ + TXT_SEQ
#define CONDN 1024
#define BLOCKN 1024        // IMG_SEQ - COND
#define SBSN 1152          // SEQ - COND
#define EPSV 1e-5f

// ---------------- device scratch (no allocation allowed) ----------------
__device__ float g_Q[SEQN * DIMN];
__device__ float g_K[SEQN * DIMN];
__device__ float g_V[SEQN * DIMN];
__device__ float g_part[8 * CONDN * 192];
__device__ __half g_Ah[SEQN * DIMN];    // fp16 [img; txt] activations
__device__ __half g_Oh[SEQN * DIMN];    // fp16 attention output
__device__ __half g_Qh[SEQN * DIMN];
__device__ __half g_Kh[SEQN * DIMN];
__device__ __half g_Vth[DIMN * SEQN];   // per head: [d=128][seq] fp16

// ---------------- helpers ----------------
__device__ __forceinline__ uint32_t pack_h2(float x, float y) {
    __half2 h = __floats2half2_rn(x, y);
    return *(uint32_t*)&h;
}

__device__ __forceinline__ void mma_f16(float c[4], const uint32_t a[4],
                                        uint32_t b0, uint32_t b1) {
    asm volatile(
        "mma.sync.aligned.m16n8k16.row.col.f32.f16.f16.f32 "
        "{%0,%1,%2,%3}, {%4,%5,%6,%7}, {%8,%9}, {%0,%1,%2,%3};"
        : "+f"(c[0]), "+f"(c[1]), "+f"(c[2]), "+f"(c[3])
        : "r"(a[0]), "r"(a[1]), "r"(a[2]), "r"(a[3]),
          "r"(b0), "r"(b1));
}

__device__ __forceinline__ void ldsm4(uint32_t& r0, uint32_t& r1,
                                      uint32_t& r2, uint32_t& r3, uint32_t addr) {
    asm volatile("ldmatrix.sync.aligned.m8n8.x4.shared.b16 {%0,%1,%2,%3}, [%4];"
                 : "=r"(r0), "=r"(r1), "=r"(r2), "=r"(r3) : "r"(addr));
}

__device__ __forceinline__ void cp_async16(uint32_t dst_smem, const void* src) {
    asm volatile("cp.async.cg.shared.global [%0], [%1], 16;"
                 :: "r"(dst_smem), "l"(src));
}
__device__ __forceinline__ void cp_commit() {
    asm volatile("cp.async.commit_group;" ::: "memory");
}
template <int N>
__device__ __forceinline__ void cp_wait() {
    asm volatile("cp.async.wait_group %0;" :: "n"(N) : "memory");
}

#define HLD 40   // halves per smem row (20 words -> conflict-free ldmatrix)

// ---------------- fp32 -> fp16 streaming convert (img ++ txt) ---------------
__global__ __launch_bounds__(256) void tofp16_kernel(const float* __restrict__ a,
                                                     const float* __restrict__ b,
                                                     int na4, int tot4,
                                                     __half* __restrict__ dst) {
    int i = blockIdx.x * blockDim.x + threadIdx.x;
    if (i >= tot4) return;
    const float* src = (i < na4) ? &a[(size_t)i * 4] : &b[(size_t)(i - na4) * 4];
    float4 v = *(const float4*)src;
    *(uint2*)&dst[(size_t)i * 4] = make_uint2(pack_h2(v.x, v.y), pack_h2(v.z, v.w));
}

// ===== async fp16 projection GEMM + fused LoRA-up ============================
#define PJ_AS0 0
#define PJ_AS1 10240
#define PJ_BS  20480
#define PJ_BST0 30720
#define PJ_BST1 47104
#define PJ_BYTES 63488

__global__ __launch_bounds__(256, 2) void proj_gemm3h(
    const __half* __restrict__ Ain,
    const float* __restrict__ Wa0, const float* __restrict__ Wb0, float* __restrict__ C0,
    const float* __restrict__ Wa1, const float* __restrict__ Wb1, float* __restrict__ C1,
    const float* __restrict__ Wa2, const float* __restrict__ Wb2, float* __restrict__ C2,
    const float* __restrict__ part,
    const float* __restrict__ up0, const float* __restrict__ up1,
    const float* __restrict__ up2,
    int Msplit, int N, int K, int lora, int remap) {
    extern __shared__ char smc[];
    const uint32_t sbase = (uint32_t)__cvta_generic_to_shared(smc);
    __half* Bs = (__half*)(smc + PJ_BS);
    const uint32_t bs_base = sbase + PJ_BS;

    const int tid = threadIdx.x;
    const int lane = tid & 31;
    const int warp = tid >> 5;
    const int wm = warp & 3;
    const int wn = warp >> 2;
    const int lrow = lane >> 2;
    const int lcol = lane & 3;
    const int row0 = blockIdx.y * 128;
    const int col0 = blockIdx.x * 128;
    const int z = blockIdx.z;

    const float* W;
    float* C;
    const float* up;
    if (z == 0)      { W = (row0 < Msplit) ? Wa0 : Wb0; C = C0; up = up0; }
    else if (z == 1) { W = (row0 < Msplit) ? Wa1 : Wb1; C = C1; up = up1; }
    else             { W = (row0 < Msplit) ? Wa2 : Wb2; C = C2; up = up2; }

    int row_out0 = row0;
    if (remap) {
        if (row0 >= IMG_SEQ)      row_out0 = row0 - CONDN;
        else if (row0 >= BLOCKN)  row_out0 = row0 + TXT_SEQ;
    }

    float c[2][8][4];
#pragma unroll
    for (int i = 0; i < 2; i++)
#pragma unroll
        for (int j = 0; j < 8; j++)
#pragma unroll
            for (int r = 0; r < 4; r++) c[i][j][r] = 0.f;

    const int al_row = wm * 32 + (lane & 15);
    const int al_k   = 8 * (lane >> 4);
    const int bl_tile = lane >> 4;
    const int bl_row  = lane & 7;
    const int bl_k    = 8 * ((lane >> 3) & 1);

    auto compute_block = [&](uint32_t a_base) {
#pragma unroll
        for (int ks = 0; ks < 2; ks++) {
            const int kb = ks * 16;
            uint32_t a[2][4];
#pragma unroll
            for (int mi = 0; mi < 2; mi++) {
                uint32_t addr = a_base +
                    (uint32_t)(((al_row + mi * 16) * HLD) + kb + al_k) * 2;
                ldsm4(a[mi][0], a[mi][1], a[mi][2], a[mi][3], addr);
            }
            uint32_t b[8][2];
#pragma unroll
            for (int j = 0; j < 4; j++) {
                int brow = wn * 64 + (2 * j + bl_tile) * 8 + bl_row;
                uint32_t addr = bs_base + (uint32_t)(brow * HLD + kb + bl_k) * 2;
                ldsm4(b[2 * j][0], b[2 * j][1], b[2 * j + 1][0], b[2 * j + 1][1], addr);
            }
#pragma unroll
            for (int mi = 0; mi < 2; mi++)
#pragma unroll
                for (int ni = 0; ni < 8; ni++)
                    mma_f16(c[mi][ni], a[mi], b[ni][0], b[ni][1]);
        }
    };

    auto issue_tile = [&](int kt, int stg) {
        const int k0 = kt * 32;
        const __half* asrc = Ain + (size_t)row0 * K + k0;
        const uint32_t adst = sbase + (stg ? PJ_AS1 : PJ_AS0);
#pragma unroll
        for (int f = 0; f < 2; f++) {
            int id = tid + f * 256;
            int r = id >> 2;
            int cc = id & 3;
            cp_async16(adst + (uint32_t)(r * 80 + cc * 16),
                       asrc + (size_t)r * K + cc * 8);
        }
        const float* wsrc = W + (size_t)col0 * K + k0;
        const uint32_t bdst = sbase + (stg ? PJ_BST1 : PJ_BST0);
#pragma unroll
        for (int f = 0; f < 4; f++) {
            int id = tid + f * 256;
            int r = id >> 3;
            int cc = id & 7;
            cp_async16(bdst + (uint32_t)(r * 128 + cc * 16),
                       wsrc + (size_t)r * K + cc * 4);
        }
        cp_commit();
    };

    auto convert_B = [&](int stg) {
        const float* bst = (const float*)(smc + (stg ? PJ_BST1 : PJ_BST0));
#pragma unroll
        for (int f = 0; f < 4; f++) {
            int id = tid + f * 256;
            int r = id >> 3;
            int kq = (id & 7) << 2;
            float4 v = *(const float4*)&bst[r * 32 + kq];
            *(uint2*)&Bs[r * HLD + kq] =
                make_uint2(pack_h2(v.x, v.y), pack_h2(v.z, v.w));
        }
    };

    const int iters = K / 32;
    issue_tile(0, 0);

    for (int it = 0; it < iters; it++) {
        const int stg = it & 1;
        if (it + 1 < iters) {
            issue_tile(it + 1, stg ^ 1);
            cp_wait<1>();
        } else {
            cp_wait<0>();
        }
        convert_B(stg);
        __syncthreads();
        compute_block(sbase + (stg ? PJ_AS1 : PJ_AS0));
        __syncthreads();
    }

    if (lora && row0 >= BLOCKN && row0 < IMG_SEQ) {
        __half* As0 = (__half*)(smc + PJ_AS0);
        const int arow0 = row0 - BLOCKN;
#pragma unroll
        for (int e = 0; e < 2; e++) {
            const int k0 = e * 32;
#pragma unroll
            for (int f = 0; f < 4; f++) {
                int id = tid + f * 256;
                int r = id >> 3;
                int kq = (id & 7) << 2;
                const float* pa = part + (size_t)(arow0 + r) * 192 + z * 64 + k0 + kq;
                float4 va = *(const float4*)pa;
#pragma unroll
                for (int s = 1; s < 8; s++) {
                    float4 t = *(const float4*)(pa + (size_t)s * CONDN * 192);
                    va.x += t.x; va.y += t.y; va.z += t.z; va.w += t.w;
                }
                *(uint2*)&As0[r * HLD + kq] =
                    make_uint2(pack_h2(va.x, va.y), pack_h2(va.z, va.w));
                float4 vb = *(const float4*)&up[(size_t)(col0 + r) * 64 + k0 + kq];
                *(uint2*)&Bs[r * HLD + kq] =
                    make_uint2(pack_h2(vb.x, vb.y), pack_h2(vb.z, vb.w));
            }
            __syncthreads();
            compute_block(sbase + PJ_AS0);
            __syncthreads();
        }
    }

#pragma unroll
    for (int mi = 0; mi < 2; mi++)
#pragma unroll
        for (int ni = 0; ni < 8; ni++) {
            int gr = row_out0 + wm * 32 + mi * 16 + lrow;
            int gc = col0 + wn * 64 + ni * 8 + lcol * 2;
            *(float2*)&C[(size_t)gr * N + gc] =
                make_float2(c[mi][ni][0], c[mi][ni][1]);
            *(float2*)&C[(size_t)(gr + 8) * N + gc] =
                make_float2(c[mi][ni][2], c[mi][ni][3]);
        }
}

// ===== fp16 LoRA up-projection with inline 8-way partial sum ================
__global__ __launch_bounds__(256) void up_sum_gemm_acc_h(
    const float* __restrict__ part,
    const float* __restrict__ W,
    float* __restrict__ C, int N) {
    __shared__ __half As[128 * HLD];
    __shared__ __half Bs[128 * HLD];

    const int tid = threadIdx.x;
    const int lane = tid & 31;
    const int warp = tid >> 5;
    const int wm = warp & 3;
    const int wn = warp >> 2;
    const int lrow = lane >> 2;
    const int lcol = lane & 3;
    const int row0 = blockIdx.y * 128;
    const int col0 = blockIdx.x * 128;

    float c[2][8][4];
#pragma unroll
    for (int i = 0; i < 2; i++)
#pragma unroll
        for (int j = 0; j < 8; j++)
#pragma unroll
            for (int r = 0; r < 4; r++) c[i][j][r] = 0.f;

    for (int k0 = 0; k0 < 64; k0 += 32) {
#pragma unroll
        for (int f = 0; f < 4; f++) {
            int id = tid + f * 256;
            int r = id >> 3;
            int kq = (id & 7) << 2;
            const float* pa = part + (size_t)(row0 + r) * 64 + k0 + kq;
            float4 va = *(const float4*)pa;
#pragma unroll
            for (int s = 1; s < 8; s++) {
                float4 t = *(const float4*)(pa + (size_t)s * CONDN * 64);
                va.x += t.x; va.y += t.y; va.z += t.z; va.w += t.w;
            }
            *(uint2*)&As[r * HLD + kq] =
                make_uint2(pack_h2(va.x, va.y), pack_h2(va.z, va.w));
            float4 vb = *(const float4*)&W[(size_t)(col0 + r) * 64 + k0 + kq];
            *(uint2*)&Bs[r * HLD + kq] =
                make_uint2(pack_h2(vb.x, vb.y), pack_h2(vb.z, vb.w));
        }
        __syncthreads();

#pragma unroll
        for (int ks = 0; ks < 2; ks++) {
            const int kb = ks * 16 + 2 * lcol;
            uint32_t a[2][4];
#pragma unroll
            for (int mi = 0; mi < 2; mi++) {
                int ar = wm * 32 + mi * 16 + lrow;
                a[mi][0] = *(const uint32_t*)&As[ar * HLD + kb];
                a[mi][1] = *(const uint32_t*)&As[(ar + 8) * HLD + kb];
                a[mi][2] = *(const uint32_t*)&As[ar * HLD + kb + 8];
                a[mi][3] = *(const uint32_t*)&As[(ar + 8) * HLD + kb + 8];
            }
            uint32_t b[8][2];
#pragma unroll
            for (int ni = 0; ni < 8; ni++) {
                int br = wn * 64 + ni * 8 + lrow;
                b[ni][0] = *(const uint32_t*)&Bs[br * HLD + kb];
                b[ni][1] = *(const uint32_t*)&Bs[br * HLD + kb + 8];
            }
#pragma unroll
            for (int mi = 0; mi < 2; mi++)
#pragma unroll
                for (int ni = 0; ni < 8; ni++)
                    mma_f16(c[mi][ni], a[mi], b[ni][0], b[ni][1]);
        }
        __syncthreads();
    }

#pragma unroll
    for (int mi = 0; mi < 2; mi++)
#pragma unroll
        for (int ni = 0; ni < 8; ni++) {
            int gr = row0 + wm * 32 + mi * 16 + lrow;
            int gc = col0 + wn * 64 + ni * 8 + lcol * 2;
            float2* p0 = (float2*)&C[(size_t)gr * N + gc];
            float2* p1 = (float2*)&C[(size_t)(gr + 8) * N + gc];
            float2 o0 = *p0, o1 = *p1;
            o0.x += c[mi][ni][0]; o0.y += c[mi][ni][1];
            o1.x += c[mi][ni][2]; o1.y += c[mi][ni][3];
            *p0 = o0; *p1 = o1;
        }
}

// ===== split-K LoRA down-projection, templated A type ========================
template <typename TA>
__global__ __launch_bounds__(256) void down_gemm_t(const TA* __restrict__ A,
                                                   const float* __restrict__ w0,
                                                   const float* __restrict__ w1,
                                                   const float* __restrict__ w2,
                                                   float* __restrict__ part,
                                                   int M, int Ntot, int Kfull) {
    __shared__ __half As[128 * HLD];
    __shared__ __half Ws[64 * HLD];

    const int cb = blockIdx.x, mb = blockIdx.y, sp = blockIdx.z;
    const int Kc = Kfull >> 3;
    const int kbase = sp * Kc;
    const float* W = (cb == 0) ? w0 : (cb == 1 ? w1 : w2);

    const int tid = threadIdx.x;
    const int lane = tid & 31;
    const int warp = tid >> 5;
    const int wm = warp & 3;
    const int wn = warp >> 2;
    const int lrow = lane >> 2;
    const int lcol = lane & 3;

    float c[2][4][4];
#pragma unroll
    for (int i = 0; i < 2; i++)
#pragma unroll
        for (int j = 0; j < 4; j++)
#pragma unroll
            for (int r = 0; r < 4; r++) c[i][j][r] = 0.f;

    for (int k0 = 0; k0 < Kc; k0 += 32) {
#pragma unroll
        for (int f = 0; f < 4; f++) {
            int id = tid + f * 256;
            int r = id >> 3;
            int kq = (id & 7) << 2;
            const TA* pa = &A[(size_t)(mb * 128 + r) * Kfull + kbase + k0 + kq];
            if (sizeof(TA) == 2) {
                *(uint2*)&As[r * HLD + kq] = *(const uint2*)pa;
            } else {
                float4 va = *(const float4*)pa;
                *(uint2*)&As[r * HLD + kq] =
                    make_uint2(pack_h2(va.x, va.y), pack_h2(va.z, va.w));
            }
        }
#pragma unroll
        for (int f = 0; f < 2; f++) {
            int id = tid + f * 256;
            int r = id >> 3;
            int kq = (id & 7) << 2;
            float4 vb = *(const float4*)&W[(size_t)r * Kfull + kbase + k0 + kq];
            *(uint2*)&Ws[r * HLD + kq] =
                make_uint2(pack_h2(vb.x, vb.y), pack_h2(vb.z, vb.w));
        }
        __syncthreads();

#pragma unroll
        for (int ks = 0; ks < 2; ks++) {
            const int kb = ks * 16 + 2 * lcol;
            uint32_t a[2][4];
#pragma unroll
            for (int mi = 0; mi < 2; mi++) {
                int ar = wm * 32 + mi * 16 + lrow;
                a[mi][0] = *(const uint32_t*)&As[ar * HLD + kb];
                a[mi][1] = *(const uint32_t*)&As[(ar + 8) * HLD + kb];
                a[mi][2] = *(const uint32_t*)&As[ar * HLD + kb + 8];
                a[mi][3] = *(const uint32_t*)&As[(ar + 8) * HLD + kb + 8];
            }
            uint32_t b[4][2];
#pragma unroll
            for (int ni = 0; ni < 4; ni++) {
                int br = wn * 32 + ni * 8 + lrow;
                b[ni][0] = *(const uint32_t*)&Ws[br * HLD + kb];
                b[ni][1] = *(const uint32_t*)&Ws[br * HLD + kb + 8];
            }
#pragma unroll
            for (int mi = 0; mi < 2; mi++)
#pragma unroll
                for (int ni = 0; ni < 4; ni++)
                    mma_f16(c[mi][ni], a[mi], b[ni][0], b[ni][1]);
        }
        __syncthreads();
    }

    float* basep = part + (size_t)sp * M * Ntot;
#pragma unroll
    for (int mi = 0; mi < 2; mi++)
#pragma unroll
        for (int ni = 0; ni < 4; ni++) {
            int gr = mb * 128 + wm * 32 + mi * 16 + lrow;
            int gc = cb * 64 + wn * 32 + ni * 8 + lcol * 2;
            *(float2*)&basep[(size_t)gr * Ntot + gc] =
                make_float2(c[mi][ni][0], c[mi][ni][1]);
            *(float2*)&basep[(size_t)(gr + 8) * Ntot + gc] =
                make_float2(c[mi][ni][2], c[mi][ni][3]);
        }
}

// ---------------- fused RMS + rope -> fp16 Qh (pre-scaled), Kh --------------
__global__ __launch_bounds__(256) void rmsrope_kernel(
    const float* __restrict__ Q, const float* __restrict__ K,
    __half* __restrict__ Qh, __half* __restrict__ Kh,
    const float* __restrict__ rope,
    const float* __restrict__ gq, const float* __restrict__ gk,
    const float* __restrict__ gqt, const float* __restrict__ gkt) {
    const int row = blockIdx.x;
    const int tid = threadIdx.x;
    __shared__ float sbuf[18];

    const float* qrow = Q + (size_t)row * DIMN;
    const float* krow = K + (size_t)row * DIMN;
    __half* qh = Qh + (size_t)row * DIMN;
    __half* kh = Kh + (size_t)row * DIMN;

    float sq = 0.f, sk = 0.f;
    for (int c4 = tid; c4 < DIMN / 4; c4 += 256) {
        float4 q = *(const float4*)&qrow[c4 * 4];
        sq += q.x * q.x + q.y * q.y + q.z * q.z + q.w * q.w;
        float4 kk = *(const float4*)&krow[c4 * 4];
        sk += kk.x * kk.x + kk.y * kk.y + kk.z * kk.z + kk.w * kk.w;
    }
#pragma unroll
    for (int o = 16; o > 0; o >>= 1) {
        sq += __shfl_xor_sync(0xffffffffu, sq, o);
        sk += __shfl_xor_sync(0xffffffffu, sk, o);
    }
    int w = tid >> 5;
    if ((tid & 31) == 0) { sbuf[w] = sq; sbuf[8 + w] = sk; }
    __syncthreads();
    if (tid == 0) {
        float a = 0.f, b = 0.f;
        for (int i = 0; i < 8; i++) { a += sbuf[i]; b += sbuf[8 + i]; }
        sbuf[16] = a; sbuf[17] = b;
    }
    __syncthreads();
    const float scale = 0.08838834764831844f;
    const float invq = rsqrtf(sbuf[16] / (float)DIMN + EPSV);
    const float invk = rsqrtf(sbuf[17] / (float)DIMN + EPSV);
    const float* gQ = (row < IMG_SEQ) ? gq : gqt;
    const float* gK = (row < IMG_SEQ) ? gk : gkt;
    const float* rp = rope + (size_t)row * 256;

    for (int pi = tid; pi < DIMN / 2; pi += 256) {
        int c0 = pi * 2;
        int j = pi & 63;
        float4 r = *(const float4*)&rp[j * 4];
        float x0 = qrow[c0] * invq * gQ[c0];
        float x1 = qrow[c0 + 1] * invq * gQ[c0 + 1];
        *(uint32_t*)&qh[c0] = pack_h2(scale * (r.x * x0 + r.y * x1),
                                      scale * (r.z * x0 + r.w * x1));
        float y0 = krow[c0] * invk * gK[c0];
        float y1 = krow[c0 + 1] * invk * gK[c0 + 1];
        *(uint32_t*)&kh[c0] = pack_h2(r.x * y0 + r.y * y1,
                                      r.z * y0 + r.w * y1);
    }
}

// ---------------- V transpose+convert: V[j][h*128+d] -> Vth[h][d][j] --------
__global__ __launch_bounds__(256) void vtrans_kernel(const float* __restrict__ V,
                                                     __half* __restrict__ Vth) {
    __shared__ float ts[64][65];
    const int jb = blockIdx.x * 64;
    const int db = blockIdx.y * 64;
    const int tid = threadIdx.x;
#pragma unroll
    for (int f = 0; f < 16; f++) {
        int idx = tid + f * 256;
        int j = idx >> 6, d = idx & 63;
        ts[j][d] = V[(size_t)(jb + j) * DIMN + db + d];
    }
    __syncthreads();
    const int head = db >> 7;
    const int dh = db & 127;
#pragma unroll
    for (int f = 0; f < 16; f++) {
        int idx = tid + f * 256;
        int d = idx >> 6, j = idx & 63;
        Vth[(size_t)head * 128 * SEQN + (size_t)(dh + d) * SEQN + jb + j] =
            __float2half_rn(ts[j][d]);
    }
}

// -- flash attention: register-resident P + LPT (heavy-first) CTA ordering ---
#define KLD 136
#define VLD 72
#define FB_KS0 0
#define FB_KS1 17408
#define FB_VT0 34816
#define FB_VT1 53248
#define FB_BYTES 71680
#define QB_HEAVY 9       // q-blocks 0..8 attend all 34 tiles (SBSN/128)

__global__ __launch_bounds__(256) void flash_mma(const __half* __restrict__ Qh,
                                                 const __half* __restrict__ Kh,
                                                 const __half* __restrict__ Vth,
                                                 __half* __restrict__ Oh) {
    extern __shared__ char smc[];
    const uint32_t sbase = (uint32_t)__cvta_generic_to_shared(smc);

    const int tid = threadIdx.x;
    const int lane = tid & 31;
    const int warp = tid >> 5;
    const int lrow = lane >> 2;
    const int lcol = lane & 3;

    // LPT remap: flat index -> all heavy q-blocks first, then light ones.
    int flat = blockIdx.x + (SEQN / 128) * blockIdx.y;   // grid (17, 16)
    int qb, head;
    if (flat < QB_HEAVY * HEADS) {          // 144 heavy CTAs (34 K-tiles)
        qb = flat % QB_HEAVY;
        head = flat / QB_HEAVY;
    } else {                                 // 128 light CTAs (16 K-tiles)
        int r = flat - QB_HEAVY * HEADS;
        qb = QB_HEAVY + (r & 7);
        head = r >> 3;
    }
    const int qrow0 = qb * 128;
    const size_t hoff = (size_t)head * HD;
    const __half* Vh = Vth + (size_t)head * 128 * SEQN;

    const int bl_tile = lane >> 4;
    const int bl_row  = lane & 7;
    const int bl_k    = 8 * ((lane >> 3) & 1);

    uint32_t qa[8][4];
    {
        const __half* qb_ = Qh + (size_t)(qrow0 + warp * 16) * DIMN + hoff;
#pragma unroll
        for (int ks = 0; ks < 8; ks++) {
            int kb = ks * 16 + 2 * lcol;
            qa[ks][0] = *(const uint32_t*)&qb_[(size_t)lrow * DIMN + kb];
            qa[ks][1] = *(const uint32_t*)&qb_[(size_t)(lrow + 8) * DIMN + kb];
            qa[ks][2] = *(const uint32_t*)&qb_[(size_t)lrow * DIMN + kb + 8];
            qa[ks][3] = *(const uint32_t*)&qb_[(size_t)(lrow + 8) * DIMN + kb + 8];
        }
    }

    float o[16][4];
#pragma unroll
    for (int ni = 0; ni < 16; ni++)
#pragma unroll
        for (int r = 0; r < 4; r++) o[ni][r] = 0.f;
    float m0 = -INFINITY, m1 = -INFINITY, l0 = 0.f, l1 = 0.f;

    const int kt0 = (qrow0 >= SBSN) ? (SBSN / 64) : 0;
    const int ktN = SEQN / 64;

    auto issue_tile = [&](int kt, int stg) {
        const int kr0 = kt * 64;
        const __half* ksrc = Kh + (size_t)kr0 * DIMN + hoff;
        const uint32_t kdst = sbase + (stg ? FB_KS1 : FB_KS0);
#pragma unroll
        for (int f = 0; f < 4; f++) {
            int id = tid + f * 256;
            int r = id >> 4;
            int cc = id & 15;
            cp_async16(kdst + (uint32_t)(r * KLD + cc * 8) * 2,
                       ksrc + (size_t)r * DIMN + cc * 8);
        }
        const __half* vsrc = Vh + kr0;
        const uint32_t vdst = sbase + (stg ? FB_VT1 : FB_VT0);
#pragma unroll
        for (int f = 0; f < 4; f++) {
            int id = tid + f * 256;
            int d = id >> 3;
            int cc = id & 7;
            cp_async16(vdst + (uint32_t)(d * VLD + cc * 8) * 2,
                       vsrc + (size_t)d * SEQN + cc * 8);
        }
        cp_commit();
    };

    issue_tile(kt0, kt0 & 1);

    for (int kt = kt0; kt < ktN; kt++) {
        const int stg = kt & 1;
        if (kt + 1 < ktN) {
            issue_tile(kt + 1, stg ^ 1);
            cp_wait<1>();
        } else {
            cp_wait<0>();
        }
        __syncthreads();
        const uint32_t ks_base = sbase + (stg ? FB_KS1 : FB_KS0);
        const uint32_t vt_base = sbase + (stg ? FB_VT1 : FB_VT0);

        float s[8][4];
#pragma unroll
        for (int ni = 0; ni < 8; ni++)
#pragma unroll
            for (int r = 0; r < 4; r++) s[ni][r] = 0.f;
#pragma unroll
        for (int ks = 0; ks < 8; ks++) {
            const int kb = ks * 16;
            uint32_t b[8][2];
#pragma unroll
            for (int j = 0; j < 4; j++) {
                int brow = (2 * j + bl_tile) * 8 + bl_row;
                uint32_t addr = ks_base + (uint32_t)(brow * KLD + kb + bl_k) * 2;
                ldsm4(b[2 * j][0], b[2 * j][1], b[2 * j + 1][0], b[2 * j + 1][1], addr);
            }
#pragma unroll
            for (int ni = 0; ni < 8; ni++)
                mma_f16(s[ni], qa[ks], b[ni][0], b[ni][1]);
        }

        float mt0 = -INFINITY, mt1 = -INFINITY;
#pragma unroll
        for (int ni = 0; ni < 8; ni++) {
            mt0 = fmaxf(mt0, fmaxf(s[ni][0], s[ni][1]));
            mt1 = fmaxf(mt1, fmaxf(s[ni][2], s[ni][3]));
        }
#pragma unroll
        for (int off = 1; off <= 2; off <<= 1) {
            mt0 = fmaxf(mt0, __shfl_xor_sync(0xffffffffu, mt0, off));
            mt1 = fmaxf(mt1, __shfl_xor_sync(0xffffffffu, mt1, off));
        }
        float mn0 = fmaxf(m0, mt0), mn1 = fmaxf(m1, mt1);
        float corr0 = __expf(m0 - mn0), corr1 = __expf(m1 - mn1);
        m0 = mn0; m1 = mn1;

        uint32_t ph[8][2];
        float ps0 = 0.f, ps1 = 0.f;
#pragma unroll
        for (int ni = 0; ni < 8; ni++) {
            __half2 h01 = __floats2half2_rn(__expf(s[ni][0] - mn0),
                                            __expf(s[ni][1] - mn0));
            __half2 h23 = __floats2half2_rn(__expf(s[ni][2] - mn1),
                                            __expf(s[ni][3] - mn1));
            ps0 += __low2float(h01) + __high2float(h01);
            ps1 += __low2float(h23) + __high2float(h23);
            ph[ni][0] = *(uint32_t*)&h01;
            ph[ni][1] = *(uint32_t*)&h23;
        }
#pragma unroll
        for (int off = 1; off <= 2; off <<= 1) {
            ps0 += __shfl_xor_sync(0xffffffffu, ps0, off);
            ps1 += __shfl_xor_sync(0xffffffffu, ps1, off);
        }
        l0 = l0 * corr0 + ps0;
        l1 = l1 * corr1 + ps1;
#pragma unroll
        for (int ni = 0; ni < 16; ni++) {
            o[ni][0] *= corr0; o[ni][1] *= corr0;
            o[ni][2] *= corr1; o[ni][3] *= corr1;
        }

#pragma unroll
        for (int ks = 0; ks < 4; ks++) {
            const int kb = ks * 16;
            uint32_t a[4];
            a[0] = ph[2 * ks][0];
            a[1] = ph[2 * ks][1];
            a[2] = ph[2 * ks + 1][0];
            a[3] = ph[2 * ks + 1][1];
#pragma unroll
            for (int j = 0; j < 8; j++) {
                int brow = (2 * j + bl_tile) * 8 + bl_row;
                uint32_t addr = vt_base + (uint32_t)(brow * VLD + kb + bl_k) * 2;
                uint32_t b0, b1, b2, b3;
                ldsm4(b0, b1, b2, b3, addr);
                mma_f16(o[2 * j], a, b0, b1);
                mma_f16(o[2 * j + 1], a, b2, b3);
            }
        }
        __syncthreads();
    }

    const float inv0 = 1.f / l0, inv1 = 1.f / l1;
    const int gr0 = qrow0 + warp * 16 + lrow;
#pragma unroll
    for (int ni = 0; ni < 16; ni++) {
        int gc = ni * 8 + lcol * 2;
        *(uint32_t*)&Oh[(size_t)gr0 * DIMN + hoff + gc] =
            pack_h2(o[ni][0] * inv0, o[ni][1] * inv0);
        *(uint32_t*)&Oh[(size_t)(gr0 + 8) * DIMN + hoff + gc] =
            pack_h2(o[ni][2] * inv1, o[ni][3] * inv1);
    }
}

// ---------------- launch ----------------
extern "C" void kernel_launch(void* const* d_in, const int* in_sizes, int n_in,
                              void* d_out, int out_size) {
    const float* img  = (const float*)d_in[0];
    const float* txt  = (const float*)d_in[1];
    const float* rope = (const float*)d_in[2];
    const float* wq   = (const float*)d_in[3];
    const float* wk   = (const float*)d_in[4];
    const float* wv   = (const float*)d_in[5];
    const float* wo   = (const float*)d_in[6];
    const float* wq_t = (const float*)d_in[7];
    const float* wk_t = (const float*)d_in[8];
    const float* wv_t = (const float*)d_in[9];
    const float* wo_t = (const float*)d_in[10];
    const float* gq   = (const float*)d_in[11];
    const float* gk   = (const float*)d_in[12];
    const float* gqt  = (const float*)d_in[13];
    const float* gkt  = (const float*)d_in[14];
    const float* q_down = (const float*)d_in[15];
    const float* q_up   = (const float*)d_in[16];
    const float* k_down = (const float*)d_in[17];
    const float* k_up   = (const float*)d_in[18];
    const float* v_down = (const float*)d_in[19];
    const float* v_up   = (const float*)d_in[20];
    const float* p_down = (const float*)d_in[21];
    const float* p_up   = (const float*)d_in[22];
    float* out = (float*)d_out;

    float *Q, *K, *V, *part;
    __half *Ah, *Oh, *Qh, *Kh, *Vth;
    cudaGetSymbolAddress((void**)&Q,    g_Q);
    cudaGetSymbolAddress((void**)&K,    g_K);
    cudaGetSymbolAddress((void**)&V,    g_V);
    cudaGetSymbolAddress((void**)&part, g_part);
    cudaGetSymbolAddress((void**)&Ah,   g_Ah);
    cudaGetSymbolAddress((void**)&Oh,   g_Oh);
    cudaGetSymbolAddress((void**)&Qh,   g_Qh);
    cudaGetSymbolAddress((void**)&Kh,   g_Kh);
    cudaGetSymbolAddress((void**)&Vth,  g_Vth);

    float* out_cond = out + (size_t)SBSN * DIMN;

    cudaFuncSetAttribute(proj_gemm3h, cudaFuncAttributeMaxDynamicSharedMemorySize,
                         PJ_BYTES);
    cudaFuncSetAttribute(flash_mma, cudaFuncAttributeMaxDynamicSharedMemorySize,
                         FB_BYTES);

    // 0) activations -> fp16 [img; txt]
    {
        int na4 = IMG_SEQ * DIMN / 4;
        int tot4 = SEQN * DIMN / 4;
        tofp16_kernel<<<(tot4 + 255) / 256, 256>>>(img, txt, na4, tot4, Ah);
    }

    // 1) fused LoRA down-projections (q/k/v), split-K 8-way -> partials
    down_gemm_t<__half><<<dim3(3, CONDN / 128, 8), 256>>>(
        Ah + (size_t)BLOCKN * DIMN, q_down, k_down, v_down,
        part, CONDN, 192, DIMN);

    // 2) QKV projections in ONE launch, LoRA-up FUSED into cond-row epilogue
    proj_gemm3h<<<dim3(DIMN / 128, SEQN / 128, 3), 256, PJ_BYTES>>>(
        Ah,
        wq, wq_t, Q,
        wk, wk_t, K,
        wv, wv_t, V,
        part, q_up, k_up, v_up,
        IMG_SEQ, DIMN, DIMN, 1, 0);

    // 3) RMS + rope -> fp16 Qh (pre-scaled), Kh ; V -> transposed fp16 Vth
    rmsrope_kernel<<<SEQN, 256>>>(Q, K, Qh, Kh, rope, gq, gk, gqt, gkt);
    vtrans_kernel<<<dim3(SEQN / 64, DIMN / 64), 256>>>(V, Vth);

    // 4) flash attention (register-resident P, LPT ordering) -> fp16 Oh
    flash_mma<<<dim3(SEQN / 128, HEADS), 256, FB_BYTES>>>(Qh, Kh, Vth, Oh);

    // 5) output projection, written DIRECTLY in output layout [img|text|cond]
    proj_gemm3h<<<dim3(DIMN / 128, SEQN / 128, 1), 256, PJ_BYTES>>>(
        Oh,
        wo, wo_t, out,
        wo, wo_t, out,
        wo, wo_t, out,
        part, q_up, k_up, v_up,
        IMG_SEQ, DIMN, DIMN, 0, 1);

    // 6) post-projection LoRA on cond region of out (down -> fused-sum up)
    down_gemm_t<float><<<dim3(1, CONDN / 128, 8), 256>>>(
        out_cond, p_down, p_down, p_down, part, CONDN, 64, DIMN);
    up_sum_gemm_acc_h<<<dim3(DIMN / 128, CONDN / 128), 256>>>(part, p_up,
                                                              out_cond, DIMN);
}

// round 17
// speedup vs baseline: 1.1050x; 1.0126x over previous
#include <cuda_runtime.h>
#include <cuda_fp16.h>
#include <math.h>
#include <stdint.h>

// ---------------- problem constants ----------------
#define DIMN 2048
#define HEADS 16
#define HD 128
#define RANKN 64
#define IMG_SEQ 2048
#define TXT_SEQ 128
#define SEQN 2176          // IMG_SEQ + TXT_SEQ
#define CONDN 1024
#define BLOCKN 1024        // IMG_SEQ - COND
#define SBSN 1152          // SEQ - COND
#define EPSV 1e-5f

// ---------------- device scratch (no allocation allowed) ----------------
__device__ float g_Q[SEQN * DIMN];
__device__ float g_K[SEQN * DIMN];
__device__ float g_V[SEQN * DIMN];
__device__ float g_part[8 * CONDN * 192];
__device__ __half g_Ah[SEQN * DIMN];    // fp16 [img; txt] activations
__device__ __half g_Oh[SEQN * DIMN];    // fp16 attention output
__device__ __half g_Qh[SEQN * DIMN];
__device__ __half g_Kh[SEQN * DIMN];
__device__ __half g_Vth[DIMN * SEQN];   // per head: [d=128][seq] fp16

// ---------------- helpers ----------------
__device__ __forceinline__ uint32_t pack_h2(float x, float y) {
    __half2 h = __floats2half2_rn(x, y);
    return *(uint32_t*)&h;
}

__device__ __forceinline__ void mma_f16(float c[4], const uint32_t a[4],
                                        uint32_t b0, uint32_t b1) {
    asm volatile(
        "mma.sync.aligned.m16n8k16.row.col.f32.f16.f16.f32 "
        "{%0,%1,%2,%3}, {%4,%5,%6,%7}, {%8,%9}, {%0,%1,%2,%3};"
        : "+f"(c[0]), "+f"(c[1]), "+f"(c[2]), "+f"(c[3])
        : "r"(a[0]), "r"(a[1]), "r"(a[2]), "r"(a[3]),
          "r"(b0), "r"(b1));
}

__device__ __forceinline__ void ldsm4(uint32_t& r0, uint32_t& r1,
                                      uint32_t& r2, uint32_t& r3, uint32_t addr) {
    asm volatile("ldmatrix.sync.aligned.m8n8.x4.shared.b16 {%0,%1,%2,%3}, [%4];"
                 : "=r"(r0), "=r"(r1), "=r"(r2), "=r"(r3) : "r"(addr));
}

__device__ __forceinline__ void cp_async16(uint32_t dst_smem, const void* src) {
    asm volatile("cp.async.cg.shared.global [%0], [%1], 16;"
                 :: "r"(dst_smem), "l"(src));
}
__device__ __forceinline__ void cp_commit() {
    asm volatile("cp.async.commit_group;" ::: "memory");
}
template <int N>
__device__ __forceinline__ void cp_wait() {
    asm volatile("cp.async.wait_group %0;" :: "n"(N) : "memory");
}

#define HLD 40   // halves per smem row (20 words -> conflict-free ldmatrix)

// ---------------- fp32 -> fp16 streaming convert (img ++ txt) ---------------
__global__ __launch_bounds__(256) void tofp16_kernel(const float* __restrict__ a,
                                                     const float* __restrict__ b,
                                                     int na4, int tot4,
                                                     __half* __restrict__ dst) {
    int i = blockIdx.x * blockDim.x + threadIdx.x;
    if (i >= tot4) return;
    const float* src = (i < na4) ? &a[(size_t)i * 4] : &b[(size_t)(i - na4) * 4];
    float4 v = *(const float4*)src;
    *(uint2*)&dst[(size_t)i * 4] = make_uint2(pack_h2(v.x, v.y), pack_h2(v.z, v.w));
}

// ===== async fp16 projection GEMM + fused LoRA-up ============================
#define PJ_AS0 0
#define PJ_AS1 10240
#define PJ_BS  20480
#define PJ_BST0 30720
#define PJ_BST1 47104
#define PJ_BYTES 63488

__global__ __launch_bounds__(256, 2) void proj_gemm3h(
    const __half* __restrict__ Ain,
    const float* __restrict__ Wa0, const float* __restrict__ Wb0, float* __restrict__ C0,
    const float* __restrict__ Wa1, const float* __restrict__ Wb1, float* __restrict__ C1,
    const float* __restrict__ Wa2, const float* __restrict__ Wb2, float* __restrict__ C2,
    const float* __restrict__ part,
    const float* __restrict__ up0, const float* __restrict__ up1,
    const float* __restrict__ up2,
    int Msplit, int N, int K, int lora, int remap) {
    extern __shared__ char smc[];
    const uint32_t sbase = (uint32_t)__cvta_generic_to_shared(smc);
    __half* Bs = (__half*)(smc + PJ_BS);
    const uint32_t bs_base = sbase + PJ_BS;

    const int tid = threadIdx.x;
    const int lane = tid & 31;
    const int warp = tid >> 5;
    const int wm = warp & 3;
    const int wn = warp >> 2;
    const int lrow = lane >> 2;
    const int lcol = lane & 3;
    const int row0 = blockIdx.y * 128;
    const int col0 = blockIdx.x * 128;
    const int z = blockIdx.z;

    const float* W;
    float* C;
    const float* up;
    if (z == 0)      { W = (row0 < Msplit) ? Wa0 : Wb0; C = C0; up = up0; }
    else if (z == 1) { W = (row0 < Msplit) ? Wa1 : Wb1; C = C1; up = up1; }
    else             { W = (row0 < Msplit) ? Wa2 : Wb2; C = C2; up = up2; }

    int row_out0 = row0;
    if (remap) {
        if (row0 >= IMG_SEQ)      row_out0 = row0 - CONDN;
        else if (row0 >= BLOCKN)  row_out0 = row0 + TXT_SEQ;
    }

    float c[2][8][4];
#pragma unroll
    for (int i = 0; i < 2; i++)
#pragma unroll
        for (int j = 0; j < 8; j++)
#pragma unroll
            for (int r = 0; r < 4; r++) c[i][j][r] = 0.f;

    const int al_row = wm * 32 + (lane & 15);
    const int al_k   = 8 * (lane >> 4);
    const int bl_tile = lane >> 4;
    const int bl_row  = lane & 7;
    const int bl_k    = 8 * ((lane >> 3) & 1);

    auto compute_block = [&](uint32_t a_base) {
#pragma unroll
        for (int ks = 0; ks < 2; ks++) {
            const int kb = ks * 16;
            uint32_t a[2][4];
#pragma unroll
            for (int mi = 0; mi < 2; mi++) {
                uint32_t addr = a_base +
                    (uint32_t)(((al_row + mi * 16) * HLD) + kb + al_k) * 2;
                ldsm4(a[mi][0], a[mi][1], a[mi][2], a[mi][3], addr);
            }
            uint32_t b[8][2];
#pragma unroll
            for (int j = 0; j < 4; j++) {
                int brow = wn * 64 + (2 * j + bl_tile) * 8 + bl_row;
                uint32_t addr = bs_base + (uint32_t)(brow * HLD + kb + bl_k) * 2;
                ldsm4(b[2 * j][0], b[2 * j][1], b[2 * j + 1][0], b[2 * j + 1][1], addr);
            }
#pragma unroll
            for (int mi = 0; mi < 2; mi++)
#pragma unroll
                for (int ni = 0; ni < 8; ni++)
                    mma_f16(c[mi][ni], a[mi], b[ni][0], b[ni][1]);
        }
    };

    auto issue_tile = [&](int kt, int stg) {
        const int k0 = kt * 32;
        const __half* asrc = Ain + (size_t)row0 * K + k0;
        const uint32_t adst = sbase + (stg ? PJ_AS1 : PJ_AS0);
#pragma unroll
        for (int f = 0; f < 2; f++) {
            int id = tid + f * 256;
            int r = id >> 2;
            int cc = id & 3;
            cp_async16(adst + (uint32_t)(r * 80 + cc * 16),
                       asrc + (size_t)r * K + cc * 8);
        }
        const float* wsrc = W + (size_t)col0 * K + k0;
        const uint32_t bdst = sbase + (stg ? PJ_BST1 : PJ_BST0);
#pragma unroll
        for (int f = 0; f < 4; f++) {
            int id = tid + f * 256;
            int r = id >> 3;
            int cc = id & 7;
            cp_async16(bdst + (uint32_t)(r * 128 + cc * 16),
                       wsrc + (size_t)r * K + cc * 4);
        }
        cp_commit();
    };

    auto convert_B = [&](int stg) {
        const float* bst = (const float*)(smc + (stg ? PJ_BST1 : PJ_BST0));
#pragma unroll
        for (int f = 0; f < 4; f++) {
            int id = tid + f * 256;
            int r = id >> 3;
            int kq = (id & 7) << 2;
            float4 v = *(const float4*)&bst[r * 32 + kq];
            *(uint2*)&Bs[r * HLD + kq] =
                make_uint2(pack_h2(v.x, v.y), pack_h2(v.z, v.w));
        }
    };

    const int iters = K / 32;
    issue_tile(0, 0);

    for (int it = 0; it < iters; it++) {
        const int stg = it & 1;
        if (it + 1 < iters) {
            issue_tile(it + 1, stg ^ 1);
            cp_wait<1>();
        } else {
            cp_wait<0>();
        }
        convert_B(stg);
        __syncthreads();
        compute_block(sbase + (stg ? PJ_AS1 : PJ_AS0));
        __syncthreads();
    }

    if (lora && row0 >= BLOCKN && row0 < IMG_SEQ) {
        __half* As0 = (__half*)(smc + PJ_AS0);
        const int arow0 = row0 - BLOCKN;
#pragma unroll
        for (int e = 0; e < 2; e++) {
            const int k0 = e * 32;
#pragma unroll
            for (int f = 0; f < 4; f++) {
                int id = tid + f * 256;
                int r = id >> 3;
                int kq = (id & 7) << 2;
                const float* pa = part + (size_t)(arow0 + r) * 192 + z * 64 + k0 + kq;
                float4 va = *(const float4*)pa;
#pragma unroll
                for (int s = 1; s < 8; s++) {
                    float4 t = *(const float4*)(pa + (size_t)s * CONDN * 192);
                    va.x += t.x; va.y += t.y; va.z += t.z; va.w += t.w;
                }
                *(uint2*)&As0[r * HLD + kq] =
                    make_uint2(pack_h2(va.x, va.y), pack_h2(va.z, va.w));
                float4 vb = *(const float4*)&up[(size_t)(col0 + r) * 64 + k0 + kq];
                *(uint2*)&Bs[r * HLD + kq] =
                    make_uint2(pack_h2(vb.x, vb.y), pack_h2(vb.z, vb.w));
            }
            __syncthreads();
            compute_block(sbase + PJ_AS0);
            __syncthreads();
        }
    }

#pragma unroll
    for (int mi = 0; mi < 2; mi++)
#pragma unroll
        for (int ni = 0; ni < 8; ni++) {
            int gr = row_out0 + wm * 32 + mi * 16 + lrow;
            int gc = col0 + wn * 64 + ni * 8 + lcol * 2;
            *(float2*)&C[(size_t)gr * N + gc] =
                make_float2(c[mi][ni][0], c[mi][ni][1]);
            *(float2*)&C[(size_t)(gr + 8) * N + gc] =
                make_float2(c[mi][ni][2], c[mi][ni][3]);
        }
}

// ===== fp16 LoRA up-projection with inline 8-way partial sum ================
__global__ __launch_bounds__(256) void up_sum_gemm_acc_h(
    const float* __restrict__ part,
    const float* __restrict__ W,
    float* __restrict__ C, int N) {
    __shared__ __half As[128 * HLD];
    __shared__ __half Bs[128 * HLD];

    const int tid = threadIdx.x;
    const int lane = tid & 31;
    const int warp = tid >> 5;
    const int wm = warp & 3;
    const int wn = warp >> 2;
    const int lrow = lane >> 2;
    const int lcol = lane & 3;
    const int row0 = blockIdx.y * 128;
    const int col0 = blockIdx.x * 128;

    float c[2][8][4];
#pragma unroll
    for (int i = 0; i < 2; i++)
#pragma unroll
        for (int j = 0; j < 8; j++)
#pragma unroll
            for (int r = 0; r < 4; r++) c[i][j][r] = 0.f;

    for (int k0 = 0; k0 < 64; k0 += 32) {
#pragma unroll
        for (int f = 0; f < 4; f++) {
            int id = tid + f * 256;
            int r = id >> 3;
            int kq = (id & 7) << 2;
            const float* pa = part + (size_t)(row0 + r) * 64 + k0 + kq;
            float4 va = *(const float4*)pa;
#pragma unroll
            for (int s = 1; s < 8; s++) {
                float4 t = *(const float4*)(pa + (size_t)s * CONDN * 64);
                va.x += t.x; va.y += t.y; va.z += t.z; va.w += t.w;
            }
            *(uint2*)&As[r * HLD + kq] =
                make_uint2(pack_h2(va.x, va.y), pack_h2(va.z, va.w));
            float4 vb = *(const float4*)&W[(size_t)(col0 + r) * 64 + k0 + kq];
            *(uint2*)&Bs[r * HLD + kq] =
                make_uint2(pack_h2(vb.x, vb.y), pack_h2(vb.z, vb.w));
        }
        __syncthreads();

#pragma unroll
        for (int ks = 0; ks < 2; ks++) {
            const int kb = ks * 16 + 2 * lcol;
            uint32_t a[2][4];
#pragma unroll
            for (int mi = 0; mi < 2; mi++) {
                int ar = wm * 32 + mi * 16 + lrow;
                a[mi][0] = *(const uint32_t*)&As[ar * HLD + kb];
                a[mi][1] = *(const uint32_t*)&As[(ar + 8) * HLD + kb];
                a[mi][2] = *(const uint32_t*)&As[ar * HLD + kb + 8];
                a[mi][3] = *(const uint32_t*)&As[(ar + 8) * HLD + kb + 8];
            }
            uint32_t b[8][2];
#pragma unroll
            for (int ni = 0; ni < 8; ni++) {
                int br = wn * 64 + ni * 8 + lrow;
                b[ni][0] = *(const uint32_t*)&Bs[br * HLD + kb];
                b[ni][1] = *(const uint32_t*)&Bs[br * HLD + kb + 8];
            }
#pragma unroll
            for (int mi = 0; mi < 2; mi++)
#pragma unroll
                for (int ni = 0; ni < 8; ni++)
                    mma_f16(c[mi][ni], a[mi], b[ni][0], b[ni][1]);
        }
        __syncthreads();
    }

#pragma unroll
    for (int mi = 0; mi < 2; mi++)
#pragma unroll
        for (int ni = 0; ni < 8; ni++) {
            int gr = row0 + wm * 32 + mi * 16 + lrow;
            int gc = col0 + wn * 64 + ni * 8 + lcol * 2;
            float2* p0 = (float2*)&C[(size_t)gr * N + gc];
            float2* p1 = (float2*)&C[(size_t)(gr + 8) * N + gc];
            float2 o0 = *p0, o1 = *p1;
            o0.x += c[mi][ni][0]; o0.y += c[mi][ni][1];
            o1.x += c[mi][ni][2]; o1.y += c[mi][ni][3];
            *p0 = o0; *p1 = o1;
        }
}

// ===== async split-K LoRA down-projection, templated A type ==================
// cp.async double-buffered producers (A fp16 direct / fp32 staged; W staged).
#define DG_AS0   0          // fp16 A buf, 128*HLD*2 = 10240
#define DG_AS1   10240
#define DG_WS    20480      // fp16 W buf, 64*HLD*2 = 5120
#define DG_ASTG0 25600      // fp32 A staging (float path), 128*32*4 = 16384
#define DG_ASTG1 41984
#define DG_WSTG0 58368      // fp32 W staging, 64*32*4 = 8192
#define DG_WSTG1 66560
#define DG_BYTES 74752

template <typename TA>
__global__ __launch_bounds__(256) void down_gemm_a(const TA* __restrict__ A,
                                                   const float* __restrict__ w0,
                                                   const float* __restrict__ w1,
                                                   const float* __restrict__ w2,
                                                   float* __restrict__ part,
                                                   int M, int Ntot, int Kfull) {
    extern __shared__ char smc[];
    const uint32_t sbase = (uint32_t)__cvta_generic_to_shared(smc);
    __half* Ws = (__half*)(smc + DG_WS);

    const int cb = blockIdx.x, mb = blockIdx.y, sp = blockIdx.z;
    const int Kc = Kfull >> 3;
    const int kbase = sp * Kc;
    const float* W = (cb == 0) ? w0 : (cb == 1 ? w1 : w2);

    const int tid = threadIdx.x;
    const int lane = tid & 31;
    const int warp = tid >> 5;
    const int wm = warp & 3;
    const int wn = warp >> 2;
    const int lrow = lane >> 2;
    const int lcol = lane & 3;

    float c[2][4][4];
#pragma unroll
    for (int i = 0; i < 2; i++)
#pragma unroll
        for (int j = 0; j < 4; j++)
#pragma unroll
            for (int r = 0; r < 4; r++) c[i][j][r] = 0.f;

    auto issue_tile = [&](int kt, int stg) {
        const int k0 = kbase + kt * 32;
        if (sizeof(TA) == 2) {
            const __half* asrc = (const __half*)A + (size_t)(mb * 128) * Kfull + k0;
            const uint32_t adst = sbase + (stg ? DG_AS1 : DG_AS0);
#pragma unroll
            for (int f = 0; f < 2; f++) {
                int id = tid + f * 256;
                int r = id >> 2;
                int cc = id & 3;
                cp_async16(adst + (uint32_t)(r * 80 + cc * 16),
                           asrc + (size_t)r * Kfull + cc * 8);
            }
        } else {
            const float* asrc = (const float*)A + (size_t)(mb * 128) * Kfull + k0;
            const uint32_t adst = sbase + (stg ? DG_ASTG1 : DG_ASTG0);
#pragma unroll
            for (int f = 0; f < 4; f++) {
                int id = tid + f * 256;
                int r = id >> 3;
                int cc = id & 7;
                cp_async16(adst + (uint32_t)(r * 128 + cc * 16),
                           asrc + (size_t)r * Kfull + cc * 4);
            }
        }
        const float* wsrc = W + k0;
        const uint32_t wdst = sbase + (stg ? DG_WSTG1 : DG_WSTG0);
#pragma unroll
        for (int f = 0; f < 2; f++) {
            int id = tid + f * 256;        // 0..511
            int r = id >> 3;               // 0..63
            int cc = id & 7;
            cp_async16(wdst + (uint32_t)(r * 128 + cc * 16),
                       wsrc + (size_t)r * Kfull + cc * 4);
        }
        cp_commit();
    };

    // each thread converts exactly the chunks it issued (no barrier needed)
    auto convert = [&](int stg) {
        if (sizeof(TA) == 4) {
            const float* ast = (const float*)(smc + (stg ? DG_ASTG1 : DG_ASTG0));
            __half* as = (__half*)(smc + DG_AS0);
#pragma unroll
            for (int f = 0; f < 4; f++) {
                int id = tid + f * 256;
                int r = id >> 3;
                int kq = (id & 7) << 2;
                float4 v = *(const float4*)&ast[r * 32 + kq];
                *(uint2*)&as[r * HLD + kq] =
                    make_uint2(pack_h2(v.x, v.y), pack_h2(v.z, v.w));
            }
        }
        const float* wst = (const float*)(smc + (stg ? DG_WSTG1 : DG_WSTG0));
#pragma unroll
        for (int f = 0; f < 2; f++) {
            int id = tid + f * 256;
            int r = id >> 3;
            int kq = (id & 7) << 2;
            float4 v = *(const float4*)&wst[r * 32 + kq];
            *(uint2*)&Ws[r * HLD + kq] =
                make_uint2(pack_h2(v.x, v.y), pack_h2(v.z, v.w));
        }
    };

    const int iters = Kc / 32;
    issue_tile(0, 0);

    for (int it = 0; it < iters; it++) {
        const int stg = it & 1;
        if (it + 1 < iters) {
            issue_tile(it + 1, stg ^ 1);
            cp_wait<1>();
        } else {
            cp_wait<0>();
        }
        convert(stg);
        __syncthreads();
        const __half* As = (sizeof(TA) == 2)
            ? (const __half*)(smc + (stg ? DG_AS1 : DG_AS0))
            : (const __half*)(smc + DG_AS0);

#pragma unroll
        for (int ks = 0; ks < 2; ks++) {
            const int kb = ks * 16 + 2 * lcol;
            uint32_t a[2][4];
#pragma unroll
            for (int mi = 0; mi < 2; mi++) {
                int ar = wm * 32 + mi * 16 + lrow;
                a[mi][0] = *(const uint32_t*)&As[ar * HLD + kb];
                a[mi][1] = *(const uint32_t*)&As[(ar + 8) * HLD + kb];
                a[mi][2] = *(const uint32_t*)&As[ar * HLD + kb + 8];
                a[mi][3] = *(const uint32_t*)&As[(ar + 8) * HLD + kb + 8];
            }
            uint32_t b[4][2];
#pragma unroll
            for (int ni = 0; ni < 4; ni++) {
                int br = wn * 32 + ni * 8 + lrow;
                b[ni][0] = *(const uint32_t*)&Ws[br * HLD + kb];
                b[ni][1] = *(const uint32_t*)&Ws[br * HLD + kb + 8];
            }
#pragma unroll
            for (int mi = 0; mi < 2; mi++)
#pragma unroll
                for (int ni = 0; ni < 4; ni++)
                    mma_f16(c[mi][ni], a[mi], b[ni][0], b[ni][1]);
        }
        __syncthreads();
    }

    float* basep = part + (size_t)sp * M * Ntot;
#pragma unroll
    for (int mi = 0; mi < 2; mi++)
#pragma unroll
        for (int ni = 0; ni < 4; ni++) {
            int gr = mb * 128 + wm * 32 + mi * 16 + lrow;
            int gc = cb * 64 + wn * 32 + ni * 8 + lcol * 2;
            *(float2*)&basep[(size_t)gr * Ntot + gc] =
                make_float2(c[mi][ni][0], c[mi][ni][1]);
            *(float2*)&basep[(size_t)(gr + 8) * Ntot + gc] =
                make_float2(c[mi][ni][2], c[mi][ni][3]);
        }
}

// ---------------- fused RMS + rope -> fp16 Qh (pre-scaled), Kh --------------
__global__ __launch_bounds__(256) void rmsrope_kernel(
    const float* __restrict__ Q, const float* __restrict__ K,
    __half* __restrict__ Qh, __half* __restrict__ Kh,
    const float* __restrict__ rope,
    const float* __restrict__ gq, const float* __restrict__ gk,
    const float* __restrict__ gqt, const float* __restrict__ gkt) {
    const int row = blockIdx.x;
    const int tid = threadIdx.x;
    __shared__ float sbuf[18];

    const float* qrow = Q + (size_t)row * DIMN;
    const float* krow = K + (size_t)row * DIMN;
    __half* qh = Qh + (size_t)row * DIMN;
    __half* kh = Kh + (size_t)row * DIMN;

    float sq = 0.f, sk = 0.f;
    for (int c4 = tid; c4 < DIMN / 4; c4 += 256) {
        float4 q = *(const float4*)&qrow[c4 * 4];
        sq += q.x * q.x + q.y * q.y + q.z * q.z + q.w * q.w;
        float4 kk = *(const float4*)&krow[c4 * 4];
        sk += kk.x * kk.x + kk.y * kk.y + kk.z * kk.z + kk.w * kk.w;
    }
#pragma unroll
    for (int o = 16; o > 0; o >>= 1) {
        sq += __shfl_xor_sync(0xffffffffu, sq, o);
        sk += __shfl_xor_sync(0xffffffffu, sk, o);
    }
    int w = tid >> 5;
    if ((tid & 31) == 0) { sbuf[w] = sq; sbuf[8 + w] = sk; }
    __syncthreads();
    if (tid == 0) {
        float a = 0.f, b = 0.f;
        for (int i = 0; i < 8; i++) { a += sbuf[i]; b += sbuf[8 + i]; }
        sbuf[16] = a; sbuf[17] = b;
    }
    __syncthreads();
    const float scale = 0.08838834764831844f;
    const float invq = rsqrtf(sbuf[16] / (float)DIMN + EPSV);
    const float invk = rsqrtf(sbuf[17] / (float)DIMN + EPSV);
    const float* gQ = (row < IMG_SEQ) ? gq : gqt;
    const float* gK = (row < IMG_SEQ) ? gk : gkt;
    const float* rp = rope + (size_t)row * 256;

    for (int pi = tid; pi < DIMN / 2; pi += 256) {
        int c0 = pi * 2;
        int j = pi & 63;
        float4 r = *(const float4*)&rp[j * 4];
        float x0 = qrow[c0] * invq * gQ[c0];
        float x1 = qrow[c0 + 1] * invq * gQ[c0 + 1];
        *(uint32_t*)&qh[c0] = pack_h2(scale * (r.x * x0 + r.y * x1),
                                      scale * (r.z * x0 + r.w * x1));
        float y0 = krow[c0] * invk * gK[c0];
        float y1 = krow[c0 + 1] * invk * gK[c0 + 1];
        *(uint32_t*)&kh[c0] = pack_h2(r.x * y0 + r.y * y1,
                                      r.z * y0 + r.w * y1);
    }
}

// ---------------- V transpose+convert: V[j][h*128+d] -> Vth[h][d][j] --------
__global__ __launch_bounds__(256) void vtrans_kernel(const float* __restrict__ V,
                                                     __half* __restrict__ Vth) {
    __shared__ float ts[64][65];
    const int jb = blockIdx.x * 64;
    const int db = blockIdx.y * 64;
    const int tid = threadIdx.x;
#pragma unroll
    for (int f = 0; f < 16; f++) {
        int idx = tid + f * 256;
        int j = idx >> 6, d = idx & 63;
        ts[j][d] = V[(size_t)(jb + j) * DIMN + db + d];
    }
    __syncthreads();
    const int head = db >> 7;
    const int dh = db & 127;
#pragma unroll
    for (int f = 0; f < 16; f++) {
        int idx = tid + f * 256;
        int d = idx >> 6, j = idx & 63;
        Vth[(size_t)head * 128 * SEQN + (size_t)(dh + d) * SEQN + jb + j] =
            __float2half_rn(ts[j][d]);
    }
}

// -- flash attention: register-resident P + LPT (heavy-first) CTA ordering ---
#define KLD 136
#define VLD 72
#define FB_KS0 0
#define FB_KS1 17408
#define FB_VT0 34816
#define FB_VT1 53248
#define FB_BYTES 71680
#define QB_HEAVY 9       // q-blocks 0..8 attend all 34 tiles (SBSN/128)

__global__ __launch_bounds__(256) void flash_mma(const __half* __restrict__ Qh,
                                                 const __half* __restrict__ Kh,
                                                 const __half* __restrict__ Vth,
                                                 __half* __restrict__ Oh) {
    extern __shared__ char smc[];
    const uint32_t sbase = (uint32_t)__cvta_generic_to_shared(smc);

    const int tid = threadIdx.x;
    const int lane = tid & 31;
    const int warp = tid >> 5;
    const int lrow = lane >> 2;
    const int lcol = lane & 3;

    // LPT remap: flat index -> all heavy q-blocks first, then light ones.
    int flat = blockIdx.x + (SEQN / 128) * blockIdx.y;   // grid (17, 16)
    int qb, head;
    if (flat < QB_HEAVY * HEADS) {
        qb = flat % QB_HEAVY;
        head = flat / QB_HEAVY;
    } else {
        int r = flat - QB_HEAVY * HEADS;
        qb = QB_HEAVY + (r & 7);
        head = r >> 3;
    }
    const int qrow0 = qb * 128;
    const size_t hoff = (size_t)head * HD;
    const __half* Vh = Vth + (size_t)head * 128 * SEQN;

    const int bl_tile = lane >> 4;
    const int bl_row  = lane & 7;
    const int bl_k    = 8 * ((lane >> 3) & 1);

    uint32_t qa[8][4];
    {
        const __half* qb_ = Qh + (size_t)(qrow0 + warp * 16) * DIMN + hoff;
#pragma unroll
        for (int ks = 0; ks < 8; ks++) {
            int kb = ks * 16 + 2 * lcol;
            qa[ks][0] = *(const uint32_t*)&qb_[(size_t)lrow * DIMN + kb];
            qa[ks][1] = *(const uint32_t*)&qb_[(size_t)(lrow + 8) * DIMN + kb];
            qa[ks][2] = *(const uint32_t*)&qb_[(size_t)lrow * DIMN + kb + 8];
            qa[ks][3] = *(const uint32_t*)&qb_[(size_t)(lrow + 8) * DIMN + kb + 8];
        }
    }

    float o[16][4];
#pragma unroll
    for (int ni = 0; ni < 16; ni++)
#pragma unroll
        for (int r = 0; r < 4; r++) o[ni][r] = 0.f;
    float m0 = -INFINITY, m1 = -INFINITY, l0 = 0.f, l1 = 0.f;

    const int kt0 = (qrow0 >= SBSN) ? (SBSN / 64) : 0;
    const int ktN = SEQN / 64;

    auto issue_tile = [&](int kt, int stg) {
        const int kr0 = kt * 64;
        const __half* ksrc = Kh + (size_t)kr0 * DIMN + hoff;
        const uint32_t kdst = sbase + (stg ? FB_KS1 : FB_KS0);
#pragma unroll
        for (int f = 0; f < 4; f++) {
            int id = tid + f * 256;
            int r = id >> 4;
            int cc = id & 15;
            cp_async16(kdst + (uint32_t)(r * KLD + cc * 8) * 2,
                       ksrc + (size_t)r * DIMN + cc * 8);
        }
        const __half* vsrc = Vh + kr0;
        const uint32_t vdst = sbase + (stg ? FB_VT1 : FB_VT0);
#pragma unroll
        for (int f = 0; f < 4; f++) {
            int id = tid + f * 256;
            int d = id >> 3;
            int cc = id & 7;
            cp_async16(vdst + (uint32_t)(d * VLD + cc * 8) * 2,
                       vsrc + (size_t)d * SEQN + cc * 8);
        }
        cp_commit();
    };

    issue_tile(kt0, kt0 & 1);

    for (int kt = kt0; kt < ktN; kt++) {
        const int stg = kt & 1;
        if (kt + 1 < ktN) {
            issue_tile(kt + 1, stg ^ 1);
            cp_wait<1>();
        } else {
            cp_wait<0>();
        }
        __syncthreads();
        const uint32_t ks_base = sbase + (stg ? FB_KS1 : FB_KS0);
        const uint32_t vt_base = sbase + (stg ? FB_VT1 : FB_VT0);

        float s[8][4];
#pragma unroll
        for (int ni = 0; ni < 8; ni++)
#pragma unroll
            for (int r = 0; r < 4; r++) s[ni][r] = 0.f;
#pragma unroll
        for (int ks = 0; ks < 8; ks++) {
            const int kb = ks * 16;
            uint32_t b[8][2];
#pragma unroll
            for (int j = 0; j < 4; j++) {
                int brow = (2 * j + bl_tile) * 8 + bl_row;
                uint32_t addr = ks_base + (uint32_t)(brow * KLD + kb + bl_k) * 2;
                ldsm4(b[2 * j][0], b[2 * j][1], b[2 * j + 1][0], b[2 * j + 1][1], addr);
            }
#pragma unroll
            for (int ni = 0; ni < 8; ni++)
                mma_f16(s[ni], qa[ks], b[ni][0], b[ni][1]);
        }

        float mt0 = -INFINITY, mt1 = -INFINITY;
#pragma unroll
        for (int ni = 0; ni < 8; ni++) {
            mt0 = fmaxf(mt0, fmaxf(s[ni][0], s[ni][1]));
            mt1 = fmaxf(mt1, fmaxf(s[ni][2], s[ni][3]));
        }
#pragma unroll
        for (int off = 1; off <= 2; off <<= 1) {
            mt0 = fmaxf(mt0, __shfl_xor_sync(0xffffffffu, mt0, off));
            mt1 = fmaxf(mt1, __shfl_xor_sync(0xffffffffu, mt1, off));
        }
        float mn0 = fmaxf(m0, mt0), mn1 = fmaxf(m1, mt1);
        float corr0 = __expf(m0 - mn0), corr1 = __expf(m1 - mn1);
        m0 = mn0; m1 = mn1;

        uint32_t ph[8][2];
        float ps0 = 0.f, ps1 = 0.f;
#pragma unroll
        for (int ni = 0; ni < 8; ni++) {
            __half2 h01 = __floats2half2_rn(__expf(s[ni][0] - mn0),
                                            __expf(s[ni][1] - mn0));
            __half2 h23 = __floats2half2_rn(__expf(s[ni][2] - mn1),
                                            __expf(s[ni][3] - mn1));
            ps0 += __low2float(h01) + __high2float(h01);
            ps1 += __low2float(h23) + __high2float(h23);
            ph[ni][0] = *(uint32_t*)&h01;
            ph[ni][1] = *(uint32_t*)&h23;
        }
#pragma unroll
        for (int off = 1; off <= 2; off <<= 1) {
            ps0 += __shfl_xor_sync(0xffffffffu, ps0, off);
            ps1 += __shfl_xor_sync(0xffffffffu, ps1, off);
        }
        l0 = l0 * corr0 + ps0;
        l1 = l1 * corr1 + ps1;
#pragma unroll
        for (int ni = 0; ni < 16; ni++) {
            o[ni][0] *= corr0; o[ni][1] *= corr0;
            o[ni][2] *= corr1; o[ni][3] *= corr1;
        }

#pragma unroll
        for (int ks = 0; ks < 4; ks++) {
            const int kb = ks * 16;
            uint32_t a[4];
            a[0] = ph[2 * ks][0];
            a[1] = ph[2 * ks][1];
            a[2] = ph[2 * ks + 1][0];
            a[3] = ph[2 * ks + 1][1];
#pragma unroll
            for (int j = 0; j < 8; j++) {
                int brow = (2 * j + bl_tile) * 8 + bl_row;
                uint32_t addr = vt_base + (uint32_t)(brow * VLD + kb + bl_k) * 2;
                uint32_t b0, b1, b2, b3;
                ldsm4(b0, b1, b2, b3, addr);
                mma_f16(o[2 * j], a, b0, b1);
                mma_f16(o[2 * j + 1], a, b2, b3);
            }
        }
        __syncthreads();
    }

    const float inv0 = 1.f / l0, inv1 = 1.f / l1;
    const int gr0 = qrow0 + warp * 16 + lrow;
#pragma unroll
    for (int ni = 0; ni < 16; ni++) {
        int gc = ni * 8 + lcol * 2;
        *(uint32_t*)&Oh[(size_t)gr0 * DIMN + hoff + gc] =
            pack_h2(o[ni][0] * inv0, o[ni][1] * inv0);
        *(uint32_t*)&Oh[(size_t)(gr0 + 8) * DIMN + hoff + gc] =
            pack_h2(o[ni][2] * inv1, o[ni][3] * inv1);
    }
}

// ---------------- launch ----------------
extern "C" void kernel_launch(void* const* d_in, const int* in_sizes, int n_in,
                              void* d_out, int out_size) {
    const float* img  = (const float*)d_in[0];
    const float* txt  = (const float*)d_in[1];
    const float* rope = (const float*)d_in[2];
    const float* wq   = (const float*)d_in[3];
    const float* wk   = (const float*)d_in[4];
    const float* wv   = (const float*)d_in[5];
    const float* wo   = (const float*)d_in[6];
    const float* wq_t = (const float*)d_in[7];
    const float* wk_t = (const float*)d_in[8];
    const float* wv_t = (const float*)d_in[9];
    const float* wo_t = (const float*)d_in[10];
    const float* gq   = (const float*)d_in[11];
    const float* gk   = (const float*)d_in[12];
    const float* gqt  = (const float*)d_in[13];
    const float* gkt  = (const float*)d_in[14];
    const float* q_down = (const float*)d_in[15];
    const float* q_up   = (const float*)d_in[16];
    const float* k_down = (const float*)d_in[17];
    const float* k_up   = (const float*)d_in[18];
    const float* v_down = (const float*)d_in[19];
    const float* v_up   = (const float*)d_in[20];
    const float* p_down = (const float*)d_in[21];
    const float* p_up   = (const float*)d_in[22];
    float* out = (float*)d_out;

    float *Q, *K, *V, *part;
    __half *Ah, *Oh, *Qh, *Kh, *Vth;
    cudaGetSymbolAddress((void**)&Q,    g_Q);
    cudaGetSymbolAddress((void**)&K,    g_K);
    cudaGetSymbolAddress((void**)&V,    g_V);
    cudaGetSymbolAddress((void**)&part, g_part);
    cudaGetSymbolAddress((void**)&Ah,   g_Ah);
    cudaGetSymbolAddress((void**)&Oh,   g_Oh);
    cudaGetSymbolAddress((void**)&Qh,   g_Qh);
    cudaGetSymbolAddress((void**)&Kh,   g_Kh);
    cudaGetSymbolAddress((void**)&Vth,  g_Vth);

    float* out_cond = out + (size_t)SBSN * DIMN;

    cudaFuncSetAttribute(proj_gemm3h, cudaFuncAttributeMaxDynamicSharedMemorySize,
                         PJ_BYTES);
    cudaFuncSetAttribute(flash_mma, cudaFuncAttributeMaxDynamicSharedMemorySize,
                         FB_BYTES);
    cudaFuncSetAttribute(down_gemm_a<__half>,
                         cudaFuncAttributeMaxDynamicSharedMemorySize, DG_BYTES);
    cudaFuncSetAttribute(down_gemm_a<float>,
                         cudaFuncAttributeMaxDynamicSharedMemorySize, DG_BYTES);

    // 0) activations -> fp16 [img; txt]
    {
        int na4 = IMG_SEQ * DIMN / 4;
        int tot4 = SEQN * DIMN / 4;
        tofp16_kernel<<<(tot4 + 255) / 256, 256>>>(img, txt, na4, tot4, Ah);
    }

    // 1) fused LoRA down-projections (q/k/v), split-K 8-way -> partials
    down_gemm_a<__half><<<dim3(3, CONDN / 128, 8), 256, DG_BYTES>>>(
        Ah + (size_t)BLOCKN * DIMN, q_down, k_down, v_down,
        part, CONDN, 192, DIMN);

    // 2) QKV projections in ONE launch, LoRA-up FUSED into cond-row epilogue
    proj_gemm3h<<<dim3(DIMN / 128, SEQN / 128, 3), 256, PJ_BYTES>>>(
        Ah,
        wq, wq_t, Q,
        wk, wk_t, K,
        wv, wv_t, V,
        part, q_up, k_up, v_up,
        IMG_SEQ, DIMN, DIMN, 1, 0);

    // 3) RMS + rope -> fp16 Qh (pre-scaled), Kh ; V -> transposed fp16 Vth
    rmsrope_kernel<<<SEQN, 256>>>(Q, K, Qh, Kh, rope, gq, gk, gqt, gkt);
    vtrans_kernel<<<dim3(SEQN / 64, DIMN / 64), 256>>>(V, Vth);

    // 4) flash attention (register-resident P, LPT ordering) -> fp16 Oh
    flash_mma<<<dim3(SEQN / 128, HEADS), 256, FB_BYTES>>>(Qh, Kh, Vth, Oh);

    // 5) output projection, written DIRECTLY in output layout [img|text|cond]
    proj_gemm3h<<<dim3(DIMN / 128, SEQN / 128, 1), 256, PJ_BYTES>>>(
        Oh,
        wo, wo_t, out,
        wo, wo_t, out,
        wo, wo_t, out,
        part, q_up, k_up, v_up,
        IMG_SEQ, DIMN, DIMN, 0, 1);

    // 6) post-projection LoRA on cond region of out (down -> fused-sum up)
    down_gemm_a<float><<<dim3(1, CONDN / 128, 8), 256, DG_BYTES>>>(
        out_cond, p_down, p_down, p_down, part, CONDN, 64, DIMN);
    up_sum_gemm_acc_h<<<dim3(DIMN / 128, CONDN / 128), 256>>>(part, p_up,
                                                              out_cond, DIMN);
}